// round 2
// baseline (speedup 1.0000x reference)
#include <cuda_runtime.h>
#include <cuda_bf16.h>

#define BZc 8
#define Nc 4096
#define CFc 64
#define NSc 1024
#define Kc 64
#define EPSc 1e-5f
#define NEGc -1e8f
#define Rc 0.2f

// ---------------- scratch (no allocs allowed) ----------------
__device__ int   g_fps[BZc * NSc];
__device__ int   g_nbr[BZc * NSc * Kc];          // idx | (in_radius ? 0 : 0x80000000)
__device__ float g_w0[67 * 64];
__device__ float g_bb0[64];
__device__ float g_w1[64 * 64];
__device__ float g_bb1[64];
__device__ float g_w2[64 * 128];
__device__ float g_bb2[128];

// ---------------- fold BN (eval) into weights ----------------
__global__ void fold_kernel(
    const float* __restrict__ W0, const float* __restrict__ b0, const float* __restrict__ g0,
    const float* __restrict__ be0, const float* __restrict__ rm0, const float* __restrict__ rv0,
    const float* __restrict__ W1, const float* __restrict__ b1, const float* __restrict__ g1,
    const float* __restrict__ be1, const float* __restrict__ rm1, const float* __restrict__ rv1,
    const float* __restrict__ W2, const float* __restrict__ b2, const float* __restrict__ g2,
    const float* __restrict__ be2, const float* __restrict__ rm2, const float* __restrict__ rv2)
{
    int t = blockIdx.x * blockDim.x + threadIdx.x;
    int stride = gridDim.x * blockDim.x;
    for (int i = t; i < 67 * 64; i += stride) {
        int o = i & 63;
        g_w0[i] = W0[i] * (g0[o] * rsqrtf(rv0[o] + EPSc));
    }
    for (int i = t; i < 64; i += stride) {
        float sc = g0[i] * rsqrtf(rv0[i] + EPSc);
        g_bb0[i] = (b0[i] - rm0[i]) * sc + be0[i];
    }
    for (int i = t; i < 64 * 64; i += stride) {
        int o = i & 63;
        g_w1[i] = W1[i] * (g1[o] * rsqrtf(rv1[o] + EPSc));
    }
    for (int i = t; i < 64; i += stride) {
        float sc = g1[i] * rsqrtf(rv1[i] + EPSc);
        g_bb1[i] = (b1[i] - rm1[i]) * sc + be1[i];
    }
    for (int i = t; i < 64 * 128; i += stride) {
        int o = i & 127;
        g_w2[i] = W2[i] * (g2[o] * rsqrtf(rv2[o] + EPSc));
    }
    for (int i = t; i < 128; i += stride) {
        float sc = g2[i] * rsqrtf(rv2[i] + EPSc);
        g_bb2[i] = (b2[i] - rm2[i]) * sc + be2[i];
    }
}

// ---------------- farthest point sampling ----------------
// one block per batch; pos + running dist live in SMEM; 1024 sequential argmax steps.
__global__ void __launch_bounds__(1024) fps_kernel(const float* __restrict__ pos,
                                                   float* __restrict__ out_sp)
{
    extern __shared__ float sm[];
    float* px   = sm;
    float* py   = sm + Nc;
    float* pz   = sm + 2 * Nc;
    float* dist = sm + 3 * Nc;
    __shared__ float rv_[32];
    __shared__ int   ri_[32];
    __shared__ int   scur;

    int b = blockIdx.x;
    int tid = threadIdx.x;
    int lane = tid & 31, wid = tid >> 5;
    const float* pb = pos + (size_t)b * Nc * 3;

    for (int j = tid; j < Nc; j += 1024) {
        px[j] = pb[3 * j];
        py[j] = pb[3 * j + 1];
        pz[j] = pb[3 * j + 2];
        dist[j] = 1e10f;
    }
    __syncthreads();

    int cur = 0;
    for (int s = 0; s < NSc; s++) {
        if (tid == 0) {
            g_fps[b * NSc + s] = cur;
            out_sp[(b * NSc + s) * 3 + 0] = px[cur];
            out_sp[(b * NSc + s) * 3 + 1] = py[cur];
            out_sp[(b * NSc + s) * 3 + 2] = pz[cur];
        }
        float cx = px[cur], cy = py[cur], cz = pz[cur];
        float bv = -1.0f;
        int bi = 0;
        for (int j = tid; j < Nc; j += 1024) {
            float dx = __fadd_rn(px[j], -cx);
            float dy = __fadd_rn(py[j], -cy);
            float dz = __fadd_rn(pz[j], -cz);
            float d = __fadd_rn(__fadd_rn(__fmul_rn(dx, dx), __fmul_rn(dy, dy)),
                                __fmul_rn(dz, dz));
            float nd = fminf(dist[j], d);
            dist[j] = nd;
            if (nd > bv) { bv = nd; bi = j; }   // ascending j => lowest-index tie-break
        }
        // warp argmax reduce, lowest index on ties
        for (int o = 16; o; o >>= 1) {
            float ov = __shfl_down_sync(0xffffffffu, bv, o);
            int   oi = __shfl_down_sync(0xffffffffu, bi, o);
            if (ov > bv || (ov == bv && oi < bi)) { bv = ov; bi = oi; }
        }
        if (lane == 0) { rv_[wid] = bv; ri_[wid] = bi; }
        __syncthreads();
        if (wid == 0) {
            float v = rv_[lane];
            int   i2 = ri_[lane];
            for (int o = 16; o; o >>= 1) {
                float ov = __shfl_down_sync(0xffffffffu, v, o);
                int   oi = __shfl_down_sync(0xffffffffu, i2, o);
                if (ov > v || (ov == v && oi < i2)) { v = ov; i2 = oi; }
            }
            if (lane == 0) scur = i2;
        }
        __syncthreads();
        cur = scur;
    }
}

// ---------------- exact top-K (smallest distance) via 8-bit radix select ----------------
// jax.lax.top_k(-dist): stable sort => among equal distances, lowest index wins.
__global__ void __launch_bounds__(256) select_kernel(const float* __restrict__ pos)
{
    extern __shared__ unsigned sd[];  // Nc distance bit patterns
    __shared__ int hist[256];
    __shared__ unsigned s_prefix;
    __shared__ int s_kn;
    __shared__ int s_cnt;
    __shared__ int wsum[8], wbase[8];

    int b = blockIdx.y, s = blockIdx.x, tid = threadIdx.x;
    const float* pb = pos + (size_t)b * Nc * 3;
    int ci = g_fps[b * NSc + s];
    float sx = pb[3 * ci], sy = pb[3 * ci + 1], sz = pb[3 * ci + 2];
    float ss = __fadd_rn(__fadd_rn(__fmul_rn(sx, sx), __fmul_rn(sy, sy)), __fmul_rn(sz, sz));

    int j0 = tid * 16;
    for (int j = j0; j < j0 + 16; j++) {
        float x = pb[3 * j], y = pb[3 * j + 1], z = pb[3 * j + 2];
        float pp = __fadd_rn(__fadd_rn(__fmul_rn(x, x), __fmul_rn(y, y)), __fmul_rn(z, z));
        float dot = __fadd_rn(__fadd_rn(__fmul_rn(sx, x), __fmul_rn(sy, y)), __fmul_rn(sz, z));
        float d2 = __fadd_rn(__fadd_rn(ss, pp), __fmul_rn(-2.0f, dot));
        float dd = sqrtf(fmaxf(d2, 0.0f));
        sd[j] = __float_as_uint(dd);  // non-negative float -> monotone uint key
    }

    unsigned prefix = 0;
    int kn = Kc;
    for (int pass = 0; pass < 4; pass++) {
        int shift = 24 - 8 * pass;
        hist[tid] = 0;
        __syncthreads();
        unsigned hm = pass ? (0xFFFFFFFFu << (shift + 8)) : 0u;
        for (int j = j0; j < j0 + 16; j++) {
            unsigned v = sd[j];
            if ((v & hm) == prefix) atomicAdd(&hist[(v >> shift) & 255], 1);
        }
        __syncthreads();
        if (tid == 0) {
            int cum = 0;
            for (int d = 0; d < 256; d++) {
                int c = hist[d];
                if (cum + c >= kn) {
                    s_prefix = prefix | ((unsigned)d << shift);
                    s_kn = kn - cum;
                    break;
                }
                cum += c;
            }
            if (pass == 3) s_cnt = 0;
        }
        __syncthreads();
        prefix = s_prefix;
        kn = s_kn;
    }

    unsigned kth = prefix;            // k-th smallest key; kn = #equals still needed
    int off = (b * NSc + s) * Kc;

    int myeq = 0;
    for (int j = j0; j < j0 + 16; j++) {
        unsigned v = sd[j];
        if (v < kth) {
            int p = atomicAdd(&s_cnt, 1);
            float dd = __uint_as_float(v);
            g_nbr[off + p] = j | (dd <= Rc ? 0 : 0x80000000);
        } else if (v == kth) {
            myeq++;
        }
    }
    // rank equal-valued elements by index (contiguous per-thread chunks => global order)
    int lane = tid & 31, wid = tid >> 5;
    int incl = myeq;
    for (int o = 1; o < 32; o <<= 1) {
        int t2 = __shfl_up_sync(0xffffffffu, incl, o);
        if (lane >= o) incl += t2;
    }
    if (lane == 31) wsum[wid] = incl;
    __syncthreads();
    if (tid == 0) {
        int c = 0;
        for (int w = 0; w < 8; w++) { wbase[w] = c; c += wsum[w]; }
    }
    __syncthreads();
    int r = wbase[wid] + incl - myeq;
    int slotbase = Kc - kn;
    for (int j = j0; j < j0 + 16 && r < kn; j++) {
        unsigned v = sd[j];
        if (v == kth) {
            float dd = __uint_as_float(v);
            g_nbr[off + slotbase + r] = j | (dd <= Rc ? 0 : 0x80000000);
            r++;
        }
    }
}

// ---------------- fused MLP (67->64->64->128) + masked max pool ----------------
__global__ void __launch_bounds__(256) mlp_kernel(const float* __restrict__ x,
                                                  const float* __restrict__ pos,
                                                  float* __restrict__ out,
                                                  const float* __restrict__ sp)
{
    extern __shared__ float sh[];
    float* W0s = sh;                  // 4288
    float* W1s = W0s + 67 * 64;       // 4096
    float* W2s = W1s + 64 * 64;       // 8192
    float* As  = W2s + 64 * 128;      // 64*68
    float* Bs  = As + 64 * 68;        // 64*68
    float* Mx  = Bs + 64 * 68;        // 8*128
    __shared__ int nidx[64];
    __shared__ unsigned char smask[64];
    __shared__ float scp[3];

    int b = blockIdx.y, s = blockIdx.x, tid = threadIdx.x;

    for (int i = tid; i < 67 * 64; i += 256) W0s[i] = g_w0[i];
    for (int i = tid; i < 64 * 64; i += 256) W1s[i] = g_w1[i];
    for (int i = tid; i < 64 * 128; i += 256) W2s[i] = g_w2[i];
    if (tid < 64) {
        int e = g_nbr[(b * NSc + s) * Kc + tid];
        nidx[tid] = e & 0x7FFFFFFF;
        smask[tid] = (e >= 0) ? 1 : 0;
    }
    if (tid < 3) scp[tid] = sp[(b * NSc + s) * 3 + tid];
    __syncthreads();

    const float* xb = x + (size_t)b * Nc * CFc;
    const float* pb = pos + (size_t)b * Nc * 3;
    for (int i = tid; i < 64 * 67; i += 256) {
        int k = i / 67, c = i - k * 67;
        int id = nidx[k];
        float v = (c < 3) ? (pb[3 * id + c] - scp[c]) : xb[(size_t)id * CFc + (c - 3)];
        As[k * 68 + c] = v;
    }
    __syncthreads();

    // ---- layer 1: 67 -> 64, register tile 4k x 4o ----
    {
        int kq = tid >> 4, oq = tid & 15;
        int k0 = kq * 4, o0 = oq * 4;
        float4 bias = *(const float4*)(g_bb0 + o0);
        float4 a0 = bias, a1 = bias, a2 = bias, a3 = bias;
        for (int c = 0; c < 67; c++) {
            float4 w = *(const float4*)(W0s + c * 64 + o0);
            float f0 = As[(k0 + 0) * 68 + c];
            float f1 = As[(k0 + 1) * 68 + c];
            float f2 = As[(k0 + 2) * 68 + c];
            float f3 = As[(k0 + 3) * 68 + c];
            a0.x += f0 * w.x; a0.y += f0 * w.y; a0.z += f0 * w.z; a0.w += f0 * w.w;
            a1.x += f1 * w.x; a1.y += f1 * w.y; a1.z += f1 * w.z; a1.w += f1 * w.w;
            a2.x += f2 * w.x; a2.y += f2 * w.y; a2.z += f2 * w.z; a2.w += f2 * w.w;
            a3.x += f3 * w.x; a3.y += f3 * w.y; a3.z += f3 * w.z; a3.w += f3 * w.w;
        }
        a0.x = fmaxf(a0.x, 0.f); a0.y = fmaxf(a0.y, 0.f); a0.z = fmaxf(a0.z, 0.f); a0.w = fmaxf(a0.w, 0.f);
        a1.x = fmaxf(a1.x, 0.f); a1.y = fmaxf(a1.y, 0.f); a1.z = fmaxf(a1.z, 0.f); a1.w = fmaxf(a1.w, 0.f);
        a2.x = fmaxf(a2.x, 0.f); a2.y = fmaxf(a2.y, 0.f); a2.z = fmaxf(a2.z, 0.f); a2.w = fmaxf(a2.w, 0.f);
        a3.x = fmaxf(a3.x, 0.f); a3.y = fmaxf(a3.y, 0.f); a3.z = fmaxf(a3.z, 0.f); a3.w = fmaxf(a3.w, 0.f);
        *(float4*)(Bs + (k0 + 0) * 68 + o0) = a0;
        *(float4*)(Bs + (k0 + 1) * 68 + o0) = a1;
        *(float4*)(Bs + (k0 + 2) * 68 + o0) = a2;
        *(float4*)(Bs + (k0 + 3) * 68 + o0) = a3;
    }
    __syncthreads();

    // ---- layer 2: 64 -> 64 ----
    {
        int kq = tid >> 4, oq = tid & 15;
        int k0 = kq * 4, o0 = oq * 4;
        float4 bias = *(const float4*)(g_bb1 + o0);
        float4 a0 = bias, a1 = bias, a2 = bias, a3 = bias;
        for (int c = 0; c < 64; c++) {
            float4 w = *(const float4*)(W1s + c * 64 + o0);
            float f0 = Bs[(k0 + 0) * 68 + c];
            float f1 = Bs[(k0 + 1) * 68 + c];
            float f2 = Bs[(k0 + 2) * 68 + c];
            float f3 = Bs[(k0 + 3) * 68 + c];
            a0.x += f0 * w.x; a0.y += f0 * w.y; a0.z += f0 * w.z; a0.w += f0 * w.w;
            a1.x += f1 * w.x; a1.y += f1 * w.y; a1.z += f1 * w.z; a1.w += f1 * w.w;
            a2.x += f2 * w.x; a2.y += f2 * w.y; a2.z += f2 * w.z; a2.w += f2 * w.w;
            a3.x += f3 * w.x; a3.y += f3 * w.y; a3.z += f3 * w.z; a3.w += f3 * w.w;
        }
        a0.x = fmaxf(a0.x, 0.f); a0.y = fmaxf(a0.y, 0.f); a0.z = fmaxf(a0.z, 0.f); a0.w = fmaxf(a0.w, 0.f);
        a1.x = fmaxf(a1.x, 0.f); a1.y = fmaxf(a1.y, 0.f); a1.z = fmaxf(a1.z, 0.f); a1.w = fmaxf(a1.w, 0.f);
        a2.x = fmaxf(a2.x, 0.f); a2.y = fmaxf(a2.y, 0.f); a2.z = fmaxf(a2.z, 0.f); a2.w = fmaxf(a2.w, 0.f);
        a3.x = fmaxf(a3.x, 0.f); a3.y = fmaxf(a3.y, 0.f); a3.z = fmaxf(a3.z, 0.f); a3.w = fmaxf(a3.w, 0.f);
        *(float4*)(As + (k0 + 0) * 68 + o0) = a0;
        *(float4*)(As + (k0 + 1) * 68 + o0) = a1;
        *(float4*)(As + (k0 + 2) * 68 + o0) = a2;
        *(float4*)(As + (k0 + 3) * 68 + o0) = a3;
    }
    __syncthreads();

    // ---- layer 3: 64 -> 128, fused masked max over k (8k x 4o per thread) ----
    {
        int oq = tid & 31, kq = tid >> 5;
        int o0 = oq * 4, kb = kq * 8;
        float4 bias = *(const float4*)(g_bb2 + o0);
        float4 acc[8];
#pragma unroll
        for (int i = 0; i < 8; i++) acc[i] = bias;
        for (int c = 0; c < 64; c++) {
            float4 w = *(const float4*)(W2s + c * 128 + o0);
#pragma unroll
            for (int i = 0; i < 8; i++) {
                float a = As[(kb + i) * 68 + c];
                acc[i].x += a * w.x;
                acc[i].y += a * w.y;
                acc[i].z += a * w.z;
                acc[i].w += a * w.w;
            }
        }
        float4 mx = make_float4(NEGc, NEGc, NEGc, NEGc);
#pragma unroll
        for (int i = 0; i < 8; i++) {
            if (smask[kb + i]) {
                mx.x = fmaxf(mx.x, fmaxf(acc[i].x, 0.f));
                mx.y = fmaxf(mx.y, fmaxf(acc[i].y, 0.f));
                mx.z = fmaxf(mx.z, fmaxf(acc[i].z, 0.f));
                mx.w = fmaxf(mx.w, fmaxf(acc[i].w, 0.f));
            }
        }
        *(float4*)(Mx + kq * 128 + o0) = mx;
    }
    __syncthreads();

    if (tid < 128) {
        float v = NEGc;
#pragma unroll
        for (int q = 0; q < 8; q++) v = fmaxf(v, Mx[q * 128 + tid]);
        out[(size_t)(b * NSc + s) * 128 + tid] = v;
    }
}

// ---------------- launch ----------------
extern "C" void kernel_launch(void* const* d_in, const int* in_sizes, int n_in,
                              void* d_out, int out_size)
{
    const float* x   = (const float*)d_in[0];
    const float* pos = (const float*)d_in[1];
    const float* W0 = (const float*)d_in[2];
    const float* b0 = (const float*)d_in[3];
    const float* g0 = (const float*)d_in[4];
    const float* be0 = (const float*)d_in[5];
    const float* rm0 = (const float*)d_in[6];
    const float* rv0 = (const float*)d_in[7];
    const float* W1 = (const float*)d_in[8];
    const float* b1 = (const float*)d_in[9];
    const float* g1 = (const float*)d_in[10];
    const float* be1 = (const float*)d_in[11];
    const float* rm1 = (const float*)d_in[12];
    const float* rv1 = (const float*)d_in[13];
    const float* W2 = (const float*)d_in[14];
    const float* b2 = (const float*)d_in[15];
    const float* g2 = (const float*)d_in[16];
    const float* be2 = (const float*)d_in[17];
    const float* rm2 = (const float*)d_in[18];
    const float* rv2 = (const float*)d_in[19];

    float* out = (float*)d_out;
    float* out_sp = out + (size_t)BZc * NSc * 128;  // tuple output 2: sampled_pos

    const int FPS_SMEM = 4 * Nc * 4;                         // 64 KB
    const int SEL_SMEM = Nc * 4;                             // 16 KB
    const int MLP_SMEM = (4288 + 4096 + 8192 + 4352 + 4352 + 1024) * 4;  // ~103 KB

    cudaFuncSetAttribute(fps_kernel, cudaFuncAttributeMaxDynamicSharedMemorySize, FPS_SMEM);
    cudaFuncSetAttribute(select_kernel, cudaFuncAttributeMaxDynamicSharedMemorySize, SEL_SMEM);
    cudaFuncSetAttribute(mlp_kernel, cudaFuncAttributeMaxDynamicSharedMemorySize, MLP_SMEM);

    fold_kernel<<<40, 256>>>(W0, b0, g0, be0, rm0, rv0,
                             W1, b1, g1, be1, rm1, rv1,
                             W2, b2, g2, be2, rm2, rv2);
    fps_kernel<<<BZc, 1024, FPS_SMEM>>>(pos, out_sp);
    select_kernel<<<dim3(NSc, BZc), 256, SEL_SMEM>>>(pos);
    mlp_kernel<<<dim3(NSc, BZc), 256, MLP_SMEM>>>(x, pos, out, out_sp);
}

// round 3
// speedup vs baseline: 1.3831x; 1.3831x over previous
#include <cuda_runtime.h>
#include <cuda_bf16.h>

#define BZc 8
#define Nc 4096
#define CFc 64
#define NSc 1024
#define Kc 64
#define EPSc 1e-5f
#define NEGc -1e8f
#define Rc 0.2f
#define CANDMAX 1280

// ---------------- scratch (no allocs allowed) ----------------
__device__ int   g_fps[BZc * NSc];
__device__ int   g_nbr[BZc * NSc * Kc];          // idx | (in_radius ? 0 : 0x80000000)
__device__ float g_w0[67 * 64];
__device__ float g_bb0[64];
__device__ float g_w1[64 * 64];
__device__ float g_bb1[64];
__device__ float g_w2[64 * 128];
__device__ float g_bb2[128];

// ---------------- fold BN (eval) into weights ----------------
__global__ void fold_kernel(
    const float* __restrict__ W0, const float* __restrict__ b0, const float* __restrict__ g0,
    const float* __restrict__ be0, const float* __restrict__ rm0, const float* __restrict__ rv0,
    const float* __restrict__ W1, const float* __restrict__ b1, const float* __restrict__ g1,
    const float* __restrict__ be1, const float* __restrict__ rm1, const float* __restrict__ rv1,
    const float* __restrict__ W2, const float* __restrict__ b2, const float* __restrict__ g2,
    const float* __restrict__ be2, const float* __restrict__ rm2, const float* __restrict__ rv2)
{
    int t = blockIdx.x * blockDim.x + threadIdx.x;
    int stride = gridDim.x * blockDim.x;
    for (int i = t; i < 67 * 64; i += stride) {
        int o = i & 63;
        g_w0[i] = W0[i] * (g0[o] * rsqrtf(rv0[o] + EPSc));
    }
    for (int i = t; i < 64; i += stride) {
        float sc = g0[i] * rsqrtf(rv0[i] + EPSc);
        g_bb0[i] = (b0[i] - rm0[i]) * sc + be0[i];
    }
    for (int i = t; i < 64 * 64; i += stride) {
        int o = i & 63;
        g_w1[i] = W1[i] * (g1[o] * rsqrtf(rv1[o] + EPSc));
    }
    for (int i = t; i < 64; i += stride) {
        float sc = g1[i] * rsqrtf(rv1[i] + EPSc);
        g_bb1[i] = (b1[i] - rm1[i]) * sc + be1[i];
    }
    for (int i = t; i < 64 * 128; i += stride) {
        int o = i & 127;
        g_w2[i] = W2[i] * (g2[o] * rsqrtf(rv2[o] + EPSc));
    }
    for (int i = t; i < 128; i += stride) {
        float sc = g2[i] * rsqrtf(rv2[i] + EPSc);
        g_bb2[i] = (b2[i] - rm2[i]) * sc + be2[i];
    }
}

// ---------------- farthest point sampling ----------------
// one block per batch; points AND running dist live in REGISTERS (8 pts/thread).
// smem copy of pos only for broadcasting the current centroid's coords.
__global__ void __launch_bounds__(512) fps_kernel(const float* __restrict__ pos,
                                                  float* __restrict__ out_sp)
{
    extern __shared__ float sm[];
    float* px = sm;
    float* py = sm + Nc;
    float* pz = sm + 2 * Nc;
    __shared__ float rv_[16];
    __shared__ int   ri_[16];
    __shared__ int   scur;

    int b = blockIdx.x;
    int tid = threadIdx.x;
    int lane = tid & 31, wid = tid >> 5;
    const float* pb = pos + (size_t)b * Nc * 3;

    float lx[8], ly[8], lz[8], ld[8];
#pragma unroll
    for (int k = 0; k < 8; k++) {
        int j = tid + 512 * k;
        float x = pb[3 * j], y = pb[3 * j + 1], z = pb[3 * j + 2];
        px[j] = x; py[j] = y; pz[j] = z;
        lx[k] = x; ly[k] = y; lz[k] = z; ld[k] = 1e10f;
    }
    __syncthreads();

    int cur = 0;
    for (int s = 0; s < NSc; s++) {
        float cx = px[cur], cy = py[cur], cz = pz[cur];
        if (tid == 0) {
            g_fps[b * NSc + s] = cur;
            out_sp[(b * NSc + s) * 3 + 0] = cx;
            out_sp[(b * NSc + s) * 3 + 1] = cy;
            out_sp[(b * NSc + s) * 3 + 2] = cz;
        }
        float bv = -1.0f;
        int bi = 0x7FFFFFFF;
#pragma unroll
        for (int k = 0; k < 8; k++) {
            float dx = __fadd_rn(lx[k], -cx);
            float dy = __fadd_rn(ly[k], -cy);
            float dz = __fadd_rn(lz[k], -cz);
            float d = __fadd_rn(__fadd_rn(__fmul_rn(dx, dx), __fmul_rn(dy, dy)),
                                __fmul_rn(dz, dz));
            float nd = fminf(ld[k], d);
            ld[k] = nd;
            if (nd > bv) { bv = nd; bi = tid + 512 * k; }  // ascending j => lowest index
        }
        // warp argmax (lowest index on ties)
        for (int o = 16; o; o >>= 1) {
            float ov = __shfl_down_sync(0xffffffffu, bv, o);
            int   oi = __shfl_down_sync(0xffffffffu, bi, o);
            if (ov > bv || (ov == bv && oi < bi)) { bv = ov; bi = oi; }
        }
        if (lane == 0) { rv_[wid] = bv; ri_[wid] = bi; }
        __syncthreads();
        if (wid == 0) {
            float v = (lane < 16) ? rv_[lane] : -2.0f;
            int   i2 = (lane < 16) ? ri_[lane] : 0x7FFFFFFF;
            for (int o = 8; o; o >>= 1) {
                float ov = __shfl_down_sync(0xffffffffu, v, o);
                int   oi = __shfl_down_sync(0xffffffffu, i2, o);
                if (ov > v || (ov == v && oi < i2)) { v = ov; i2 = oi; }
            }
            if (lane == 0) scur = i2;
        }
        __syncthreads();
        cur = scur;
    }
}

// ---------------- exact top-K via bit-space bisection + pairwise rank ----------------
// order of the K entries in g_nbr is irrelevant (max-pool downstream); we need the exact
// SET of k smallest by (dist, index) lexicographic, each tagged with its radius mask.
__global__ void __launch_bounds__(256) select_kernel(const float* __restrict__ pos)
{
    __shared__ int wred[8];
    __shared__ int s_tot;
    __shared__ int s_cnt;
    __shared__ unsigned cand_v[CANDMAX];
    __shared__ int      cand_i[CANDMAX];

    int b = blockIdx.y, s = blockIdx.x, tid = threadIdx.x;
    int lane = tid & 31, wid = tid >> 5;
    const float* pb = pos + (size_t)b * Nc * 3;
    int ci = g_fps[b * NSc + s];
    float sx = pb[3 * ci], sy = pb[3 * ci + 1], sz = pb[3 * ci + 2];
    float ss = __fadd_rn(__fadd_rn(__fmul_rn(sx, sx), __fmul_rn(sy, sy)), __fmul_rn(sz, sz));

    if (tid == 0) s_cnt = 0;

    unsigned vr[16];
#pragma unroll
    for (int i = 0; i < 16; i++) {
        int j = tid + 256 * i;
        float x = pb[3 * j], y = pb[3 * j + 1], z = pb[3 * j + 2];
        float pp = __fadd_rn(__fadd_rn(__fmul_rn(x, x), __fmul_rn(y, y)), __fmul_rn(z, z));
        float dot = __fadd_rn(__fadd_rn(__fmul_rn(sx, x), __fmul_rn(sy, y)), __fmul_rn(sz, z));
        float d2 = __fadd_rn(__fadd_rn(ss, pp), __fmul_rn(-2.0f, dot));
        float dd = sqrtf(fmaxf(d2, 0.0f));
        vr[i] = __float_as_uint(dd);  // non-negative float -> monotone uint key
    }

    // bisection on uint key space: find thr with 64 <= count(<thr) <= 512 (typically ~5-9 steps)
    unsigned lo = 0u, hi = 0x40000000u;  // 2.0f > sqrt(3) max distance
    unsigned thr = hi;
    for (int it = 0; it < 32; it++) {
        unsigned m = (lo + hi) >> 1;
        int c = 0;
#pragma unroll
        for (int i = 0; i < 16; i++) c += (vr[i] < m) ? 1 : 0;
        for (int o = 16; o; o >>= 1) c += __shfl_down_sync(0xffffffffu, c, o);
        if (lane == 0) wred[wid] = c;
        __syncthreads();
        if (tid == 0) {
            int t2 = 0;
#pragma unroll
            for (int w = 0; w < 8; w++) t2 += wred[w];
            s_tot = t2;
        }
        __syncthreads();
        int tot = s_tot;
        if (tot >= Kc && tot <= 512) { thr = m; break; }
        if (tot < Kc) lo = m; else hi = m;
        if (hi - lo <= 1) { thr = hi; break; }  // count(<hi) >= 64 by invariant
    }

    // gather candidates (v < thr)
#pragma unroll
    for (int i = 0; i < 16; i++) {
        if (vr[i] < thr) {
            int p = atomicAdd(&s_cnt, 1);
            if (p < CANDMAX) { cand_v[p] = vr[i]; cand_i[p] = tid + 256 * i; }
        }
    }
    __syncthreads();
    int c = s_cnt; if (c > CANDMAX) c = CANDMAX;

    // exact lexicographic (value, index) rank; ranks 0..c-1 unique; keep r < K
    int off = (b * NSc + s) * Kc;
    for (int q0 = tid; q0 < c; q0 += 256) {
        unsigned vi = cand_v[q0];
        int ji = cand_i[q0];
        int r = 0;
        for (int q = 0; q < c; q++) {
            unsigned vq = cand_v[q];
            int jq = cand_i[q];
            r += (vq < vi || (vq == vi && jq < ji)) ? 1 : 0;
        }
        if (r < Kc) {
            float ddv = __uint_as_float(vi);
            g_nbr[off + r] = ji | (ddv <= Rc ? 0 : 0x80000000);
        }
    }
}

// ---------------- fused MLP (67->64->64->128) + masked max pool ----------------
// weights streamed from global (L1-resident across CTAs); smem only for activations.
__global__ void __launch_bounds__(256, 3) mlp_kernel(const float* __restrict__ x,
                                                     const float* __restrict__ pos,
                                                     float* __restrict__ out,
                                                     const float* __restrict__ sp)
{
    __shared__ float As[64 * 68];
    __shared__ float Bs[64 * 68];
    __shared__ float Mx[8 * 128];
    __shared__ int nidx[64];
    __shared__ unsigned char smask[64];
    __shared__ float scp[3];

    int b = blockIdx.y, s = blockIdx.x, tid = threadIdx.x;

    if (tid < 64) {
        int e = g_nbr[(b * NSc + s) * Kc + tid];
        nidx[tid] = e & 0x7FFFFFFF;
        smask[tid] = (e >= 0) ? 1 : 0;
    }
    if (tid < 3) scp[tid] = sp[(b * NSc + s) * 3 + tid];
    __syncthreads();

    const float* xb = x + (size_t)b * Nc * CFc;
    const float* pb = pos + (size_t)b * Nc * 3;
    for (int i = tid; i < 64 * 67; i += 256) {
        int k = i / 67, ch = i - k * 67;
        int id = nidx[k];
        float v = (ch < 3) ? (pb[3 * id + ch] - scp[ch]) : xb[(size_t)id * CFc + (ch - 3)];
        As[k * 68 + ch] = v;
    }
    __syncthreads();

    // ---- layer 1: 67 -> 64, register tile 4k x 4o ----
    {
        int kq = tid >> 4, oq = tid & 15;
        int k0 = kq * 4, o0 = oq * 4;
        float4 bias = *(const float4*)(g_bb0 + o0);
        float4 a0 = bias, a1 = bias, a2 = bias, a3 = bias;
#pragma unroll 4
        for (int ch = 0; ch < 67; ch++) {
            float4 w = *(const float4*)(g_w0 + ch * 64 + o0);
            float f0 = As[(k0 + 0) * 68 + ch];
            float f1 = As[(k0 + 1) * 68 + ch];
            float f2 = As[(k0 + 2) * 68 + ch];
            float f3 = As[(k0 + 3) * 68 + ch];
            a0.x += f0 * w.x; a0.y += f0 * w.y; a0.z += f0 * w.z; a0.w += f0 * w.w;
            a1.x += f1 * w.x; a1.y += f1 * w.y; a1.z += f1 * w.z; a1.w += f1 * w.w;
            a2.x += f2 * w.x; a2.y += f2 * w.y; a2.z += f2 * w.z; a2.w += f2 * w.w;
            a3.x += f3 * w.x; a3.y += f3 * w.y; a3.z += f3 * w.z; a3.w += f3 * w.w;
        }
        a0.x = fmaxf(a0.x, 0.f); a0.y = fmaxf(a0.y, 0.f); a0.z = fmaxf(a0.z, 0.f); a0.w = fmaxf(a0.w, 0.f);
        a1.x = fmaxf(a1.x, 0.f); a1.y = fmaxf(a1.y, 0.f); a1.z = fmaxf(a1.z, 0.f); a1.w = fmaxf(a1.w, 0.f);
        a2.x = fmaxf(a2.x, 0.f); a2.y = fmaxf(a2.y, 0.f); a2.z = fmaxf(a2.z, 0.f); a2.w = fmaxf(a2.w, 0.f);
        a3.x = fmaxf(a3.x, 0.f); a3.y = fmaxf(a3.y, 0.f); a3.z = fmaxf(a3.z, 0.f); a3.w = fmaxf(a3.w, 0.f);
        *(float4*)(Bs + (k0 + 0) * 68 + o0) = a0;
        *(float4*)(Bs + (k0 + 1) * 68 + o0) = a1;
        *(float4*)(Bs + (k0 + 2) * 68 + o0) = a2;
        *(float4*)(Bs + (k0 + 3) * 68 + o0) = a3;
    }
    __syncthreads();

    // ---- layer 2: 64 -> 64 ----
    {
        int kq = tid >> 4, oq = tid & 15;
        int k0 = kq * 4, o0 = oq * 4;
        float4 bias = *(const float4*)(g_bb1 + o0);
        float4 a0 = bias, a1 = bias, a2 = bias, a3 = bias;
#pragma unroll 4
        for (int ch = 0; ch < 64; ch++) {
            float4 w = *(const float4*)(g_w1 + ch * 64 + o0);
            float f0 = Bs[(k0 + 0) * 68 + ch];
            float f1 = Bs[(k0 + 1) * 68 + ch];
            float f2 = Bs[(k0 + 2) * 68 + ch];
            float f3 = Bs[(k0 + 3) * 68 + ch];
            a0.x += f0 * w.x; a0.y += f0 * w.y; a0.z += f0 * w.z; a0.w += f0 * w.w;
            a1.x += f1 * w.x; a1.y += f1 * w.y; a1.z += f1 * w.z; a1.w += f1 * w.w;
            a2.x += f2 * w.x; a2.y += f2 * w.y; a2.z += f2 * w.z; a2.w += f2 * w.w;
            a3.x += f3 * w.x; a3.y += f3 * w.y; a3.z += f3 * w.z; a3.w += f3 * w.w;
        }
        a0.x = fmaxf(a0.x, 0.f); a0.y = fmaxf(a0.y, 0.f); a0.z = fmaxf(a0.z, 0.f); a0.w = fmaxf(a0.w, 0.f);
        a1.x = fmaxf(a1.x, 0.f); a1.y = fmaxf(a1.y, 0.f); a1.z = fmaxf(a1.z, 0.f); a1.w = fmaxf(a1.w, 0.f);
        a2.x = fmaxf(a2.x, 0.f); a2.y = fmaxf(a2.y, 0.f); a2.z = fmaxf(a2.z, 0.f); a2.w = fmaxf(a2.w, 0.f);
        a3.x = fmaxf(a3.x, 0.f); a3.y = fmaxf(a3.y, 0.f); a3.z = fmaxf(a3.z, 0.f); a3.w = fmaxf(a3.w, 0.f);
        *(float4*)(As + (k0 + 0) * 68 + o0) = a0;
        *(float4*)(As + (k0 + 1) * 68 + o0) = a1;
        *(float4*)(As + (k0 + 2) * 68 + o0) = a2;
        *(float4*)(As + (k0 + 3) * 68 + o0) = a3;
    }
    __syncthreads();

    // ---- layer 3: 64 -> 128, fused masked max over k (8k x 4o per thread) ----
    {
        int oq = tid & 31, kq = tid >> 5;
        int o0 = oq * 4, kb = kq * 8;
        float4 bias = *(const float4*)(g_bb2 + o0);
        float4 acc[8];
#pragma unroll
        for (int i = 0; i < 8; i++) acc[i] = bias;
#pragma unroll 2
        for (int ch = 0; ch < 64; ch++) {
            float4 w = *(const float4*)(g_w2 + ch * 128 + o0);
#pragma unroll
            for (int i = 0; i < 8; i++) {
                float a = As[(kb + i) * 68 + ch];
                acc[i].x += a * w.x;
                acc[i].y += a * w.y;
                acc[i].z += a * w.z;
                acc[i].w += a * w.w;
            }
        }
        float4 mx = make_float4(NEGc, NEGc, NEGc, NEGc);
#pragma unroll
        for (int i = 0; i < 8; i++) {
            if (smask[kb + i]) {
                mx.x = fmaxf(mx.x, fmaxf(acc[i].x, 0.f));
                mx.y = fmaxf(mx.y, fmaxf(acc[i].y, 0.f));
                mx.z = fmaxf(mx.z, fmaxf(acc[i].z, 0.f));
                mx.w = fmaxf(mx.w, fmaxf(acc[i].w, 0.f));
            }
        }
        *(float4*)(Mx + kq * 128 + o0) = mx;
    }
    __syncthreads();

    if (tid < 128) {
        float v = NEGc;
#pragma unroll
        for (int q = 0; q < 8; q++) v = fmaxf(v, Mx[q * 128 + tid]);
        out[(size_t)(b * NSc + s) * 128 + tid] = v;
    }
}

// ---------------- launch ----------------
extern "C" void kernel_launch(void* const* d_in, const int* in_sizes, int n_in,
                              void* d_out, int out_size)
{
    const float* x   = (const float*)d_in[0];
    const float* pos = (const float*)d_in[1];
    const float* W0 = (const float*)d_in[2];
    const float* b0 = (const float*)d_in[3];
    const float* g0 = (const float*)d_in[4];
    const float* be0 = (const float*)d_in[5];
    const float* rm0 = (const float*)d_in[6];
    const float* rv0 = (const float*)d_in[7];
    const float* W1 = (const float*)d_in[8];
    const float* b1 = (const float*)d_in[9];
    const float* g1 = (const float*)d_in[10];
    const float* be1 = (const float*)d_in[11];
    const float* rm1 = (const float*)d_in[12];
    const float* rv1 = (const float*)d_in[13];
    const float* W2 = (const float*)d_in[14];
    const float* b2 = (const float*)d_in[15];
    const float* g2 = (const float*)d_in[16];
    const float* be2 = (const float*)d_in[17];
    const float* rm2 = (const float*)d_in[18];
    const float* rv2 = (const float*)d_in[19];

    float* out = (float*)d_out;
    float* out_sp = out + (size_t)BZc * NSc * 128;  // tuple output 2: sampled_pos

    const int FPS_SMEM = 3 * Nc * 4;  // 48 KB dynamic

    cudaFuncSetAttribute(fps_kernel, cudaFuncAttributeMaxDynamicSharedMemorySize, FPS_SMEM);

    fold_kernel<<<40, 256>>>(W0, b0, g0, be0, rm0, rv0,
                             W1, b1, g1, be1, rm1, rv1,
                             W2, b2, g2, be2, rm2, rv2);
    fps_kernel<<<BZc, 512, FPS_SMEM>>>(pos, out_sp);
    select_kernel<<<dim3(NSc, BZc), 256>>>(pos);
    mlp_kernel<<<dim3(NSc, BZc), 256>>>(x, pos, out, out_sp);
}

// round 5
// speedup vs baseline: 1.5219x; 1.1004x over previous
#include <cuda_runtime.h>
#include <cuda_bf16.h>

#define BZc 8
#define Nc 4096
#define CFc 64
#define NSc 1024
#define Kc 64
#define EPSc 1e-5f
#define NEGc -1e8f
#define Rc 0.2f
#define CANDMAX 1280

typedef unsigned long long u64t;

// ---------------- f32x2 packed helpers (sm_100+) ----------------
__device__ __forceinline__ u64t f2pk(float lo, float hi) {
    u64t r; asm("mov.b64 %0,{%1,%2};" : "=l"(r) : "f"(lo), "f"(hi)); return r;
}
__device__ __forceinline__ u64t f2dup(float a) {
    u64t r; asm("mov.b64 %0,{%1,%1};" : "=l"(r) : "f"(a)); return r;
}
__device__ __forceinline__ void f2unpk(u64t v, float& lo, float& hi) {
    asm("mov.b64 {%0,%1},%2;" : "=f"(lo), "=f"(hi) : "l"(v));
}
__device__ __forceinline__ u64t f2add(u64t a, u64t b) {
    u64t r; asm("add.rn.f32x2 %0,%1,%2;" : "=l"(r) : "l"(a), "l"(b)); return r;
}
__device__ __forceinline__ u64t f2mul(u64t a, u64t b) {
    u64t r; asm("mul.rn.f32x2 %0,%1,%2;" : "=l"(r) : "l"(a), "l"(b)); return r;
}
__device__ __forceinline__ void f2fma(u64t& acc, u64t w, u64t a) {
    asm("fma.rn.f32x2 %0,%1,%2,%0;" : "+l"(acc) : "l"(w), "l"(a));
}

// ---------------- scratch (no allocs allowed) ----------------
__device__ int   g_fps[BZc * NSc];
__device__ int   g_nbr[BZc * NSc * Kc];          // idx | (in_radius ? 0 : 0x80000000)
__device__ __align__(16) float g_w0[67 * 64];
__device__ __align__(16) float g_bb0[64];
__device__ __align__(16) float g_w1[64 * 64];
__device__ __align__(16) float g_bb1[64];
__device__ __align__(16) float g_w2[64 * 128];
__device__ __align__(16) float g_bb2[128];

// ---------------- fold BN (eval) into weights ----------------
__global__ void fold_kernel(
    const float* __restrict__ W0, const float* __restrict__ b0, const float* __restrict__ g0,
    const float* __restrict__ be0, const float* __restrict__ rm0, const float* __restrict__ rv0,
    const float* __restrict__ W1, const float* __restrict__ b1, const float* __restrict__ g1,
    const float* __restrict__ be1, const float* __restrict__ rm1, const float* __restrict__ rv1,
    const float* __restrict__ W2, const float* __restrict__ b2, const float* __restrict__ g2,
    const float* __restrict__ be2, const float* __restrict__ rm2, const float* __restrict__ rv2)
{
    int t = blockIdx.x * blockDim.x + threadIdx.x;
    int stride = gridDim.x * blockDim.x;
    for (int i = t; i < 67 * 64; i += stride) {
        int o = i & 63;
        g_w0[i] = W0[i] * (g0[o] * rsqrtf(rv0[o] + EPSc));
    }
    for (int i = t; i < 64; i += stride) {
        float sc = g0[i] * rsqrtf(rv0[i] + EPSc);
        g_bb0[i] = (b0[i] - rm0[i]) * sc + be0[i];
    }
    for (int i = t; i < 64 * 64; i += stride) {
        int o = i & 63;
        g_w1[i] = W1[i] * (g1[o] * rsqrtf(rv1[o] + EPSc));
    }
    for (int i = t; i < 64; i += stride) {
        float sc = g1[i] * rsqrtf(rv1[i] + EPSc);
        g_bb1[i] = (b1[i] - rm1[i]) * sc + be1[i];
    }
    for (int i = t; i < 64 * 128; i += stride) {
        int o = i & 127;
        g_w2[i] = W2[i] * (g2[o] * rsqrtf(rv2[o] + EPSc));
    }
    for (int i = t; i < 128; i += stride) {
        float sc = g2[i] * rsqrtf(rv2[i] + EPSc);
        g_bb2[i] = (b2[i] - rm2[i]) * sc + be2[i];
    }
}

// ---------------- farthest point sampling ----------------
// one block per batch; points + running dist in REGISTERS, packed f32x2 pairs.
// single barrier per iteration: per-warp results parity double-buffered, final
// 16-way reduce done redundantly in every warp.
__global__ void __launch_bounds__(512) fps_kernel(const float* __restrict__ pos,
                                                  float* __restrict__ out_sp)
{
    extern __shared__ float sm[];
    float* px = sm;
    float* py = sm + Nc;
    float* pz = sm + 2 * Nc;
    __shared__ float rv_[2][16];
    __shared__ int   ri_[2][16];

    int b = blockIdx.x;
    int tid = threadIdx.x;
    int lane = tid & 31, wid = tid >> 5;
    const float* pb = pos + (size_t)b * Nc * 3;

    u64t xp[4], yp[4], zp[4];
    float ld[8];
    float tx[8], ty[8], tz[8];
#pragma unroll
    for (int k = 0; k < 8; k++) {
        int j = tid + 512 * k;
        float x = pb[3 * j], y = pb[3 * j + 1], z = pb[3 * j + 2];
        px[j] = x; py[j] = y; pz[j] = z;
        tx[k] = x; ty[k] = y; tz[k] = z; ld[k] = 1e10f;
    }
#pragma unroll
    for (int p = 0; p < 4; p++) {
        xp[p] = f2pk(tx[2 * p], tx[2 * p + 1]);
        yp[p] = f2pk(ty[2 * p], ty[2 * p + 1]);
        zp[p] = f2pk(tz[2 * p], tz[2 * p + 1]);
    }
    __syncthreads();

    int cur = 0;
    for (int s = 0; s < NSc; s++) {
        float cx = px[cur], cy = py[cur], cz = pz[cur];
        if (tid == 0) {
            g_fps[b * NSc + s] = cur;
            out_sp[(b * NSc + s) * 3 + 0] = cx;
            out_sp[(b * NSc + s) * 3 + 1] = cy;
            out_sp[(b * NSc + s) * 3 + 2] = cz;
        }
        u64t ncx = f2dup(-cx), ncy = f2dup(-cy), ncz = f2dup(-cz);
        float bv = -1.0f;
        int bi = 0x7FFFFFFF;
#pragma unroll
        for (int p = 0; p < 4; p++) {
            u64t dx = f2add(xp[p], ncx);
            u64t dy = f2add(yp[p], ncy);
            u64t dz = f2add(zp[p], ncz);
            u64t d2 = f2add(f2add(f2mul(dx, dx), f2mul(dy, dy)), f2mul(dz, dz));
            float s0, s1;
            f2unpk(d2, s0, s1);
            float nd0 = fminf(ld[2 * p], s0);
            ld[2 * p] = nd0;
            if (nd0 > bv) { bv = nd0; bi = tid + 512 * (2 * p); }     // ascending j
            float nd1 = fminf(ld[2 * p + 1], s1);
            ld[2 * p + 1] = nd1;
            if (nd1 > bv) { bv = nd1; bi = tid + 512 * (2 * p + 1); }
        }
        // warp argmax (lowest index on ties)
        for (int o = 16; o; o >>= 1) {
            float ov = __shfl_down_sync(0xffffffffu, bv, o);
            int   oi = __shfl_down_sync(0xffffffffu, bi, o);
            if (ov > bv || (ov == bv && oi < bi)) { bv = ov; bi = oi; }
        }
        int par = s & 1;
        if (lane == 0) { rv_[par][wid] = bv; ri_[par][wid] = bi; }
        __syncthreads();
        // every warp reduces the 16 per-warp winners redundantly (no 2nd barrier)
        float v = rv_[par][lane & 15];
        int   i2 = ri_[par][lane & 15];
        for (int o = 8; o; o >>= 1) {
            float ov = __shfl_down_sync(0xffffffffu, v, o);
            int   oi = __shfl_down_sync(0xffffffffu, i2, o);
            if (ov > v || (ov == v && oi < i2)) { v = ov; i2 = oi; }
        }
        cur = __shfl_sync(0xffffffffu, i2, 0);
    }
}

// ---------------- exact top-K via bit-space bisection + pairwise rank ----------------
__global__ void __launch_bounds__(256) select_kernel(const float* __restrict__ pos)
{
    __shared__ int wred[8];
    __shared__ int s_tot;
    __shared__ int s_cnt;
    __shared__ unsigned cand_v[CANDMAX];
    __shared__ int      cand_i[CANDMAX];

    int b = blockIdx.y, s = blockIdx.x, tid = threadIdx.x;
    int lane = tid & 31, wid = tid >> 5;
    const float* pb = pos + (size_t)b * Nc * 3;
    int ci = g_fps[b * NSc + s];
    float sx = pb[3 * ci], sy = pb[3 * ci + 1], sz = pb[3 * ci + 2];
    float ss = __fadd_rn(__fadd_rn(__fmul_rn(sx, sx), __fmul_rn(sy, sy)), __fmul_rn(sz, sz));

    if (tid == 0) s_cnt = 0;

    unsigned vr[16];
#pragma unroll
    for (int i = 0; i < 16; i++) {
        int j = tid + 256 * i;
        float x = pb[3 * j], y = pb[3 * j + 1], z = pb[3 * j + 2];
        float pp = __fadd_rn(__fadd_rn(__fmul_rn(x, x), __fmul_rn(y, y)), __fmul_rn(z, z));
        float dot = __fadd_rn(__fadd_rn(__fmul_rn(sx, x), __fmul_rn(sy, y)), __fmul_rn(sz, z));
        float d2 = __fadd_rn(__fadd_rn(ss, pp), __fmul_rn(-2.0f, dot));
        float dd = sqrtf(fmaxf(d2, 0.0f));
        vr[i] = __float_as_uint(dd);
    }

    unsigned lo = 0u, hi = 0x40000000u;
    unsigned thr = hi;
    for (int it = 0; it < 32; it++) {
        unsigned m = (lo + hi) >> 1;
        int c = 0;
#pragma unroll
        for (int i = 0; i < 16; i++) c += (vr[i] < m) ? 1 : 0;
        for (int o = 16; o; o >>= 1) c += __shfl_down_sync(0xffffffffu, c, o);
        if (lane == 0) wred[wid] = c;
        __syncthreads();
        if (tid == 0) {
            int t2 = 0;
#pragma unroll
            for (int w = 0; w < 8; w++) t2 += wred[w];
            s_tot = t2;
        }
        __syncthreads();
        int tot = s_tot;
        if (tot >= Kc && tot <= 512) { thr = m; break; }
        if (tot < Kc) lo = m; else hi = m;
        if (hi - lo <= 1) { thr = hi; break; }
    }

#pragma unroll
    for (int i = 0; i < 16; i++) {
        if (vr[i] < thr) {
            int p = atomicAdd(&s_cnt, 1);
            if (p < CANDMAX) { cand_v[p] = vr[i]; cand_i[p] = tid + 256 * i; }
        }
    }
    __syncthreads();
    int c = s_cnt; if (c > CANDMAX) c = CANDMAX;

    int off = (b * NSc + s) * Kc;
    for (int q0 = tid; q0 < c; q0 += 256) {
        unsigned vi = cand_v[q0];
        int ji = cand_i[q0];
        int r = 0;
        for (int q = 0; q < c; q++) {
            unsigned vq = cand_v[q];
            int jq = cand_i[q];
            r += (vq < vi || (vq == vi && jq < ji)) ? 1 : 0;
        }
        if (r < Kc) {
            float ddv = __uint_as_float(vi);
            g_nbr[off + r] = ji | (ddv <= Rc ? 0 : 0x80000000);
        }
    }
}

// ---------------- fused MLP (67->64->64->128) + masked max pool ----------------
// FFMA2 (fma.rn.f32x2) everywhere: output pairs packed in 64-bit accumulators.
__global__ void __launch_bounds__(256, 3) mlp_kernel(const float* __restrict__ x,
                                                     const float* __restrict__ pos,
                                                     float* __restrict__ out,
                                                     const float* __restrict__ sp)
{
    __shared__ float As[64 * 68];
    __shared__ float Bs[64 * 68];
    __shared__ float Mx[8 * 128];
    __shared__ int nidx[64];
    __shared__ unsigned char smask[64];
    __shared__ float scp[3];

    int b = blockIdx.y, s = blockIdx.x, tid = threadIdx.x;

    if (tid < 64) {
        int e = g_nbr[(b * NSc + s) * Kc + tid];
        nidx[tid] = e & 0x7FFFFFFF;
        smask[tid] = (e >= 0) ? 1 : 0;
    }
    if (tid < 3) scp[tid] = sp[(b * NSc + s) * 3 + tid];
    __syncthreads();

    const float* xb = x + (size_t)b * Nc * CFc;
    const float* pb = pos + (size_t)b * Nc * 3;
    for (int i = tid; i < 64 * 67; i += 256) {
        int k = i / 67, ch = i - k * 67;
        int id = nidx[k];
        float v = (ch < 3) ? (pb[3 * id + ch] - scp[ch]) : xb[(size_t)id * CFc + (ch - 3)];
        As[k * 68 + ch] = v;
    }
    __syncthreads();

    // ---- layer 1: 67 -> 64, 4k x 4o, packed pairs ----
    {
        int kq = tid >> 4, oq = tid & 15;
        int k0 = kq * 4, o0 = oq * 4;
        float4 b4 = *(const float4*)(g_bb0 + o0);
        u64t a01[4], a23[4];
#pragma unroll
        for (int i = 0; i < 4; i++) { a01[i] = f2pk(b4.x, b4.y); a23[i] = f2pk(b4.z, b4.w); }
        for (int ch = 0; ch < 64; ch += 4) {
            float4 A0 = *(const float4*)(As + (k0 + 0) * 68 + ch);
            float4 A1 = *(const float4*)(As + (k0 + 1) * 68 + ch);
            float4 A2 = *(const float4*)(As + (k0 + 2) * 68 + ch);
            float4 A3 = *(const float4*)(As + (k0 + 3) * 68 + ch);
            const float* P0 = (const float*)&A0;
            const float* P1 = (const float*)&A1;
            const float* P2 = (const float*)&A2;
            const float* P3 = (const float*)&A3;
#pragma unroll
            for (int c = 0; c < 4; c++) {
                ulonglong2 w = *(const ulonglong2*)(g_w0 + (ch + c) * 64 + o0);
                u64t p0 = f2dup(P0[c]); f2fma(a01[0], w.x, p0); f2fma(a23[0], w.y, p0);
                u64t p1 = f2dup(P1[c]); f2fma(a01[1], w.x, p1); f2fma(a23[1], w.y, p1);
                u64t p2 = f2dup(P2[c]); f2fma(a01[2], w.x, p2); f2fma(a23[2], w.y, p2);
                u64t p3 = f2dup(P3[c]); f2fma(a01[3], w.x, p3); f2fma(a23[3], w.y, p3);
            }
        }
#pragma unroll
        for (int ch = 64; ch < 67; ch++) {
            ulonglong2 w = *(const ulonglong2*)(g_w0 + ch * 64 + o0);
            u64t p0 = f2dup(As[(k0 + 0) * 68 + ch]); f2fma(a01[0], w.x, p0); f2fma(a23[0], w.y, p0);
            u64t p1 = f2dup(As[(k0 + 1) * 68 + ch]); f2fma(a01[1], w.x, p1); f2fma(a23[1], w.y, p1);
            u64t p2 = f2dup(As[(k0 + 2) * 68 + ch]); f2fma(a01[2], w.x, p2); f2fma(a23[2], w.y, p2);
            u64t p3 = f2dup(As[(k0 + 3) * 68 + ch]); f2fma(a01[3], w.x, p3); f2fma(a23[3], w.y, p3);
        }
#pragma unroll
        for (int i = 0; i < 4; i++) {
            float r0, r1, r2, r3;
            f2unpk(a01[i], r0, r1);
            f2unpk(a23[i], r2, r3);
            float4 r = make_float4(fmaxf(r0, 0.f), fmaxf(r1, 0.f), fmaxf(r2, 0.f), fmaxf(r3, 0.f));
            *(float4*)(Bs + (k0 + i) * 68 + o0) = r;
        }
    }
    __syncthreads();

    // ---- layer 2: 64 -> 64 ----
    {
        int kq = tid >> 4, oq = tid & 15;
        int k0 = kq * 4, o0 = oq * 4;
        float4 b4 = *(const float4*)(g_bb1 + o0);
        u64t a01[4], a23[4];
#pragma unroll
        for (int i = 0; i < 4; i++) { a01[i] = f2pk(b4.x, b4.y); a23[i] = f2pk(b4.z, b4.w); }
        for (int ch = 0; ch < 64; ch += 4) {
            float4 A0 = *(const float4*)(Bs + (k0 + 0) * 68 + ch);
            float4 A1 = *(const float4*)(Bs + (k0 + 1) * 68 + ch);
            float4 A2 = *(const float4*)(Bs + (k0 + 2) * 68 + ch);
            float4 A3 = *(const float4*)(Bs + (k0 + 3) * 68 + ch);
            const float* P0 = (const float*)&A0;
            const float* P1 = (const float*)&A1;
            const float* P2 = (const float*)&A2;
            const float* P3 = (const float*)&A3;
#pragma unroll
            for (int c = 0; c < 4; c++) {
                ulonglong2 w = *(const ulonglong2*)(g_w1 + (ch + c) * 64 + o0);
                u64t p0 = f2dup(P0[c]); f2fma(a01[0], w.x, p0); f2fma(a23[0], w.y, p0);
                u64t p1 = f2dup(P1[c]); f2fma(a01[1], w.x, p1); f2fma(a23[1], w.y, p1);
                u64t p2 = f2dup(P2[c]); f2fma(a01[2], w.x, p2); f2fma(a23[2], w.y, p2);
                u64t p3 = f2dup(P3[c]); f2fma(a01[3], w.x, p3); f2fma(a23[3], w.y, p3);
            }
        }
#pragma unroll
        for (int i = 0; i < 4; i++) {
            float r0, r1, r2, r3;
            f2unpk(a01[i], r0, r1);
            f2unpk(a23[i], r2, r3);
            float4 r = make_float4(fmaxf(r0, 0.f), fmaxf(r1, 0.f), fmaxf(r2, 0.f), fmaxf(r3, 0.f));
            *(float4*)(As + (k0 + i) * 68 + o0) = r;
        }
    }
    __syncthreads();

    // ---- layer 3: 64 -> 128, fused masked max over k; two k-halves of 4 ----
    {
        int oq = tid & 31, kq = tid >> 5;
        int o0 = oq * 4, kb = kq * 8;
        float4 b4 = *(const float4*)(g_bb2 + o0);
        float4 mx = make_float4(NEGc, NEGc, NEGc, NEGc);
#pragma unroll
        for (int half = 0; half < 2; half++) {
            int kh = kb + half * 4;
            u64t a01[4], a23[4];
#pragma unroll
            for (int i = 0; i < 4; i++) { a01[i] = f2pk(b4.x, b4.y); a23[i] = f2pk(b4.z, b4.w); }
            for (int ch = 0; ch < 64; ch += 2) {
                float2 A0 = *(const float2*)(As + (kh + 0) * 68 + ch);
                float2 A1 = *(const float2*)(As + (kh + 1) * 68 + ch);
                float2 A2 = *(const float2*)(As + (kh + 2) * 68 + ch);
                float2 A3 = *(const float2*)(As + (kh + 3) * 68 + ch);
                {
                    ulonglong2 w = *(const ulonglong2*)(g_w2 + ch * 128 + o0);
                    u64t p0 = f2dup(A0.x); f2fma(a01[0], w.x, p0); f2fma(a23[0], w.y, p0);
                    u64t p1 = f2dup(A1.x); f2fma(a01[1], w.x, p1); f2fma(a23[1], w.y, p1);
                    u64t p2 = f2dup(A2.x); f2fma(a01[2], w.x, p2); f2fma(a23[2], w.y, p2);
                    u64t p3 = f2dup(A3.x); f2fma(a01[3], w.x, p3); f2fma(a23[3], w.y, p3);
                }
                {
                    ulonglong2 w = *(const ulonglong2*)(g_w2 + (ch + 1) * 128 + o0);
                    u64t p0 = f2dup(A0.y); f2fma(a01[0], w.x, p0); f2fma(a23[0], w.y, p0);
                    u64t p1 = f2dup(A1.y); f2fma(a01[1], w.x, p1); f2fma(a23[1], w.y, p1);
                    u64t p2 = f2dup(A2.y); f2fma(a01[2], w.x, p2); f2fma(a23[2], w.y, p2);
                    u64t p3 = f2dup(A3.y); f2fma(a01[3], w.x, p3); f2fma(a23[3], w.y, p3);
                }
            }
#pragma unroll
            for (int i = 0; i < 4; i++) {
                if (smask[kh + i]) {
                    float r0, r1, r2, r3;
                    f2unpk(a01[i], r0, r1);
                    f2unpk(a23[i], r2, r3);
                    mx.x = fmaxf(mx.x, fmaxf(r0, 0.f));
                    mx.y = fmaxf(mx.y, fmaxf(r1, 0.f));
                    mx.z = fmaxf(mx.z, fmaxf(r2, 0.f));
                    mx.w = fmaxf(mx.w, fmaxf(r3, 0.f));
                }
            }
        }
        *(float4*)(Mx + kq * 128 + o0) = mx;
    }
    __syncthreads();

    if (tid < 128) {
        float v = NEGc;
#pragma unroll
        for (int q = 0; q < 8; q++) v = fmaxf(v, Mx[q * 128 + tid]);
        out[(size_t)(b * NSc + s) * 128 + tid] = v;
    }
}

// ---------------- launch ----------------
extern "C" void kernel_launch(void* const* d_in, const int* in_sizes, int n_in,
                              void* d_out, int out_size)
{
    const float* x   = (const float*)d_in[0];
    const float* pos = (const float*)d_in[1];
    const float* W0 = (const float*)d_in[2];
    const float* b0 = (const float*)d_in[3];
    const float* g0 = (const float*)d_in[4];
    const float* be0 = (const float*)d_in[5];
    const float* rm0 = (const float*)d_in[6];
    const float* rv0 = (const float*)d_in[7];
    const float* W1 = (const float*)d_in[8];
    const float* b1 = (const float*)d_in[9];
    const float* g1 = (const float*)d_in[10];
    const float* be1 = (const float*)d_in[11];
    const float* rm1 = (const float*)d_in[12];
    const float* rv1 = (const float*)d_in[13];
    const float* W2 = (const float*)d_in[14];
    const float* b2 = (const float*)d_in[15];
    const float* g2 = (const float*)d_in[16];
    const float* be2 = (const float*)d_in[17];
    const float* rm2 = (const float*)d_in[18];
    const float* rv2 = (const float*)d_in[19];

    float* out = (float*)d_out;
    float* out_sp = out + (size_t)BZc * NSc * 128;  // tuple output 2: sampled_pos

    const int FPS_SMEM = 3 * Nc * 4;  // 48 KB dynamic

    cudaFuncSetAttribute(fps_kernel, cudaFuncAttributeMaxDynamicSharedMemorySize, FPS_SMEM);

    fold_kernel<<<40, 256>>>(W0, b0, g0, be0, rm0, rv0,
                             W1, b1, g1, be1, rm1, rv1,
                             W2, b2, g2, be2, rm2, rv2);
    fps_kernel<<<BZc, 512, FPS_SMEM>>>(pos, out_sp);
    select_kernel<<<dim3(NSc, BZc), 256>>>(pos);
    mlp_kernel<<<dim3(NSc, BZc), 256>>>(x, pos, out, out_sp);
}

// round 6
// speedup vs baseline: 1.9924x; 1.3092x over previous
#include <cuda_runtime.h>
#include <cuda_bf16.h>

#define BZc 8
#define Nc 4096
#define CFc 64
#define NSc 1024
#define Kc 64
#define EPSc 1e-5f
#define NEGc -1e8f
#define Rc 0.2f
#define CANDMAX 1280

typedef unsigned long long u64t;

// ---------------- f32x2 packed helpers (sm_100+) ----------------
__device__ __forceinline__ u64t f2pk(float lo, float hi) {
    u64t r; asm("mov.b64 %0,{%1,%2};" : "=l"(r) : "f"(lo), "f"(hi)); return r;
}
__device__ __forceinline__ u64t f2dup(float a) {
    u64t r; asm("mov.b64 %0,{%1,%1};" : "=l"(r) : "f"(a)); return r;
}
__device__ __forceinline__ void f2unpk(u64t v, float& lo, float& hi) {
    asm("mov.b64 {%0,%1},%2;" : "=f"(lo), "=f"(hi) : "l"(v));
}
__device__ __forceinline__ u64t f2add(u64t a, u64t b) {
    u64t r; asm("add.rn.f32x2 %0,%1,%2;" : "=l"(r) : "l"(a), "l"(b)); return r;
}
__device__ __forceinline__ u64t f2mul(u64t a, u64t b) {
    u64t r; asm("mul.rn.f32x2 %0,%1,%2;" : "=l"(r) : "l"(a), "l"(b)); return r;
}
__device__ __forceinline__ void f2fma(u64t& acc, u64t w, u64t a) {
    asm("fma.rn.f32x2 %0,%1,%2,%0;" : "+l"(acc) : "l"(w), "l"(a));
}

// ---------------- scratch (no allocs allowed) ----------------
__device__ int   g_fps[BZc * NSc];
__device__ int   g_nbr[BZc * NSc * Kc];          // idx | (in_radius ? 0 : 0x80000000)
__device__ __align__(16) float g_w0[67 * 64];
__device__ __align__(16) float g_bb0[64];
__device__ __align__(16) float g_w1[64 * 64];
__device__ __align__(16) float g_bb1[64];
__device__ __align__(16) float g_w2[64 * 128];
__device__ __align__(16) float g_bb2[128];

// ---------------- fold BN (eval) into weights ----------------
__global__ void fold_kernel(
    const float* __restrict__ W0, const float* __restrict__ b0, const float* __restrict__ g0,
    const float* __restrict__ be0, const float* __restrict__ rm0, const float* __restrict__ rv0,
    const float* __restrict__ W1, const float* __restrict__ b1, const float* __restrict__ g1,
    const float* __restrict__ be1, const float* __restrict__ rm1, const float* __restrict__ rv1,
    const float* __restrict__ W2, const float* __restrict__ b2, const float* __restrict__ g2,
    const float* __restrict__ be2, const float* __restrict__ rm2, const float* __restrict__ rv2)
{
    int t = blockIdx.x * blockDim.x + threadIdx.x;
    int stride = gridDim.x * blockDim.x;
    for (int i = t; i < 67 * 64; i += stride) {
        int o = i & 63;
        g_w0[i] = W0[i] * (g0[o] * rsqrtf(rv0[o] + EPSc));
    }
    for (int i = t; i < 64; i += stride) {
        float sc = g0[i] * rsqrtf(rv0[i] + EPSc);
        g_bb0[i] = (b0[i] - rm0[i]) * sc + be0[i];
    }
    for (int i = t; i < 64 * 64; i += stride) {
        int o = i & 63;
        g_w1[i] = W1[i] * (g1[o] * rsqrtf(rv1[o] + EPSc));
    }
    for (int i = t; i < 64; i += stride) {
        float sc = g1[i] * rsqrtf(rv1[i] + EPSc);
        g_bb1[i] = (b1[i] - rm1[i]) * sc + be1[i];
    }
    for (int i = t; i < 64 * 128; i += stride) {
        int o = i & 127;
        g_w2[i] = W2[i] * (g2[o] * rsqrtf(rv2[o] + EPSc));
    }
    for (int i = t; i < 128; i += stride) {
        float sc = g2[i] * rsqrtf(rv2[i] + EPSc);
        g_bb2[i] = (b2[i] - rm2[i]) * sc + be2[i];
    }
}

// ---------------- farthest point sampling ----------------
// 256 threads, 16 pts/thread in registers (packed f32x2). Inner loop has no
// compares; tournament-tree argmax epilogue; REDUX warp/block reduce; one
// barrier per iteration (parity-buffered warp results).
__global__ void __launch_bounds__(256) fps_kernel(const float* __restrict__ pos,
                                                  float* __restrict__ out_sp)
{
    extern __shared__ float sm[];
    float* px = sm;
    float* py = sm + Nc;
    float* pz = sm + 2 * Nc;
    __shared__ unsigned rv_[2][8];
    __shared__ int      ri_[2][8];

    int b = blockIdx.x;
    int tid = threadIdx.x;
    int lane = tid & 31, wid = tid >> 5;
    const float* pb = pos + (size_t)b * Nc * 3;

    u64t xp[8], yp[8], zp[8];
    float ld[16];
#pragma unroll
    for (int p = 0; p < 8; p++) {
        int j0 = tid + 256 * (2 * p);
        int j1 = tid + 256 * (2 * p + 1);
        float x0 = pb[3 * j0], y0 = pb[3 * j0 + 1], z0 = pb[3 * j0 + 2];
        float x1 = pb[3 * j1], y1 = pb[3 * j1 + 1], z1 = pb[3 * j1 + 2];
        px[j0] = x0; py[j0] = y0; pz[j0] = z0;
        px[j1] = x1; py[j1] = y1; pz[j1] = z1;
        xp[p] = f2pk(x0, x1); yp[p] = f2pk(y0, y1); zp[p] = f2pk(z0, z1);
        ld[2 * p] = 1e10f; ld[2 * p + 1] = 1e10f;
    }
    __syncthreads();

    int cur = 0;
    for (int s = 0; s < NSc; s++) {
        float cx = px[cur], cy = py[cur], cz = pz[cur];
        if (tid == 0) {
            g_fps[b * NSc + s] = cur;
            out_sp[(b * NSc + s) * 3 + 0] = cx;
            out_sp[(b * NSc + s) * 3 + 1] = cy;
            out_sp[(b * NSc + s) * 3 + 2] = cz;
        }
        u64t ncx = f2dup(-cx), ncy = f2dup(-cy), ncz = f2dup(-cz);
#pragma unroll
        for (int p = 0; p < 8; p++) {
            u64t dx = f2add(xp[p], ncx);
            u64t dy = f2add(yp[p], ncy);
            u64t dz = f2add(zp[p], ncz);
            u64t d2 = f2add(f2add(f2mul(dx, dx), f2mul(dy, dy)), f2mul(dz, dz));
            float s0, s1;
            f2unpk(d2, s0, s1);
            ld[2 * p] = fminf(ld[2 * p], s0);
            ld[2 * p + 1] = fminf(ld[2 * p + 1], s1);
        }
        // tournament-tree argmax over 16 values, lowest index wins ties
        float v8[8]; int i8[8];
#pragma unroll
        for (int i = 0; i < 8; i++) {
            float a = ld[2 * i], bb2_ = ld[2 * i + 1];
            bool t = bb2_ > a;
            v8[i] = t ? bb2_ : a;
            i8[i] = tid + 256 * (2 * i + (t ? 1 : 0));
        }
        float v4[4]; int i4[4];
#pragma unroll
        for (int i = 0; i < 4; i++) {
            bool t = v8[2 * i + 1] > v8[2 * i];
            v4[i] = t ? v8[2 * i + 1] : v8[2 * i];
            i4[i] = t ? i8[2 * i + 1] : i8[2 * i];
        }
        float va, vb; int ia, ib;
        { bool t = v4[1] > v4[0]; va = t ? v4[1] : v4[0]; ia = t ? i4[1] : i4[0]; }
        { bool t = v4[3] > v4[2]; vb = t ? v4[3] : v4[2]; ib = t ? i4[3] : i4[2]; }
        bool tf = vb > va;
        float bv = tf ? vb : va;
        int   bi = tf ? ib : ia;

        // warp reduce: max value (dist bits >= 0, monotone), min index among maxers
        unsigned bvb = __float_as_uint(bv);
        unsigned m = __reduce_max_sync(0xffffffffu, bvb);
        unsigned cand = (bvb == m) ? (unsigned)bi : 0x7FFFFFFFu;
        unsigned wmin = __reduce_min_sync(0xffffffffu, cand);

        int par = s & 1;
        if (lane == 0) { rv_[par][wid] = m; ri_[par][wid] = (int)wmin; }
        __syncthreads();
        // block reduce redundantly in every warp (no second barrier)
        unsigned v2 = (lane < 8) ? rv_[par][lane] : 0u;
        unsigned j2 = (lane < 8) ? (unsigned)ri_[par][lane] : 0x7FFFFFFFu;
        unsigned m2 = __reduce_max_sync(0xffffffffu, v2);
        unsigned c2 = (v2 == m2) ? j2 : 0x7FFFFFFFu;
        cur = (int)__reduce_min_sync(0xffffffffu, c2);
    }
}

// ---------------- exact top-K via bit-space bisection + pairwise rank ----------------
__global__ void __launch_bounds__(256) select_kernel(const float* __restrict__ pos)
{
    __shared__ int wred[8];
    __shared__ int s_tot;
    __shared__ int s_cnt;
    __shared__ unsigned cand_v[CANDMAX];
    __shared__ int      cand_i[CANDMAX];

    int b = blockIdx.y, s = blockIdx.x, tid = threadIdx.x;
    int lane = tid & 31, wid = tid >> 5;
    const float* pb = pos + (size_t)b * Nc * 3;
    int ci = g_fps[b * NSc + s];
    float sx = pb[3 * ci], sy = pb[3 * ci + 1], sz = pb[3 * ci + 2];
    float ss = __fadd_rn(__fadd_rn(__fmul_rn(sx, sx), __fmul_rn(sy, sy)), __fmul_rn(sz, sz));

    if (tid == 0) s_cnt = 0;

    unsigned vr[16];
#pragma unroll
    for (int i = 0; i < 16; i++) {
        int j = tid + 256 * i;
        float x = pb[3 * j], y = pb[3 * j + 1], z = pb[3 * j + 2];
        float pp = __fadd_rn(__fadd_rn(__fmul_rn(x, x), __fmul_rn(y, y)), __fmul_rn(z, z));
        float dot = __fadd_rn(__fadd_rn(__fmul_rn(sx, x), __fmul_rn(sy, y)), __fmul_rn(sz, z));
        float d2 = __fadd_rn(__fadd_rn(ss, pp), __fmul_rn(-2.0f, dot));
        float dd = sqrtf(fmaxf(d2, 0.0f));
        vr[i] = __float_as_uint(dd);
    }

    unsigned lo = 0u, hi = 0x40000000u;
    unsigned thr = hi;
    for (int it = 0; it < 32; it++) {
        unsigned m = (lo + hi) >> 1;
        int c = 0;
#pragma unroll
        for (int i = 0; i < 16; i++) c += (vr[i] < m) ? 1 : 0;
        for (int o = 16; o; o >>= 1) c += __shfl_down_sync(0xffffffffu, c, o);
        if (lane == 0) wred[wid] = c;
        __syncthreads();
        if (tid == 0) {
            int t2 = 0;
#pragma unroll
            for (int w = 0; w < 8; w++) t2 += wred[w];
            s_tot = t2;
        }
        __syncthreads();
        int tot = s_tot;
        if (tot >= Kc && tot <= 256) { thr = m; break; }
        if (tot < Kc) lo = m; else hi = m;
        if (hi - lo <= 1) { thr = hi; break; }
    }

#pragma unroll
    for (int i = 0; i < 16; i++) {
        if (vr[i] < thr) {
            int p = atomicAdd(&s_cnt, 1);
            if (p < CANDMAX) { cand_v[p] = vr[i]; cand_i[p] = tid + 256 * i; }
        }
    }
    __syncthreads();
    int c = s_cnt; if (c > CANDMAX) c = CANDMAX;

    int off = (b * NSc + s) * Kc;
    for (int q0 = tid; q0 < c; q0 += 256) {
        unsigned vi = cand_v[q0];
        int ji = cand_i[q0];
        int r = 0;
        for (int q = 0; q < c; q++) {
            unsigned vq = cand_v[q];
            int jq = cand_i[q];
            r += (vq < vi || (vq == vi && jq < ji)) ? 1 : 0;
        }
        if (r < Kc) {
            float ddv = __uint_as_float(vi);
            g_nbr[off + r] = ji | (ddv <= Rc ? 0 : 0x80000000);
        }
    }
}

// ---------------- fused MLP (67->64->64->128) + masked max pool ----------------
// FFMA2 everywhere; layer 3 retiled to 4k x 8o (weights loaded ONCE, 16-lane
// o-groups halve weight wavefronts).
__global__ void __launch_bounds__(256, 3) mlp_kernel(const float* __restrict__ x,
                                                     const float* __restrict__ pos,
                                                     float* __restrict__ out,
                                                     const float* __restrict__ sp)
{
    __shared__ float As[64 * 68];
    __shared__ float Bs[64 * 68];
    __shared__ float Mx[16 * 128];
    __shared__ int nidx[64];
    __shared__ unsigned char smask[64];
    __shared__ float scp[3];

    int b = blockIdx.y, s = blockIdx.x, tid = threadIdx.x;

    if (tid < 64) {
        int e = g_nbr[(b * NSc + s) * Kc + tid];
        nidx[tid] = e & 0x7FFFFFFF;
        smask[tid] = (e >= 0) ? 1 : 0;
    }
    if (tid < 3) scp[tid] = sp[(b * NSc + s) * 3 + tid];
    __syncthreads();

    const float* xb = x + (size_t)b * Nc * CFc;
    const float* pb = pos + (size_t)b * Nc * 3;
    for (int i = tid; i < 64 * 67; i += 256) {
        int k = i / 67, ch = i - k * 67;
        int id = nidx[k];
        float v = (ch < 3) ? (pb[3 * id + ch] - scp[ch]) : xb[(size_t)id * CFc + (ch - 3)];
        As[k * 68 + ch] = v;
    }
    __syncthreads();

    // ---- layer 1: 67 -> 64, 4k x 4o, packed pairs ----
    {
        int kq = tid >> 4, oq = tid & 15;
        int k0 = kq * 4, o0 = oq * 4;
        float4 b4 = *(const float4*)(g_bb0 + o0);
        u64t a01[4], a23[4];
#pragma unroll
        for (int i = 0; i < 4; i++) { a01[i] = f2pk(b4.x, b4.y); a23[i] = f2pk(b4.z, b4.w); }
        for (int ch = 0; ch < 64; ch += 4) {
            float4 A0 = *(const float4*)(As + (k0 + 0) * 68 + ch);
            float4 A1 = *(const float4*)(As + (k0 + 1) * 68 + ch);
            float4 A2 = *(const float4*)(As + (k0 + 2) * 68 + ch);
            float4 A3 = *(const float4*)(As + (k0 + 3) * 68 + ch);
            const float* P0 = (const float*)&A0;
            const float* P1 = (const float*)&A1;
            const float* P2 = (const float*)&A2;
            const float* P3 = (const float*)&A3;
#pragma unroll
            for (int c = 0; c < 4; c++) {
                ulonglong2 w = *(const ulonglong2*)(g_w0 + (ch + c) * 64 + o0);
                u64t p0 = f2dup(P0[c]); f2fma(a01[0], w.x, p0); f2fma(a23[0], w.y, p0);
                u64t p1 = f2dup(P1[c]); f2fma(a01[1], w.x, p1); f2fma(a23[1], w.y, p1);
                u64t p2 = f2dup(P2[c]); f2fma(a01[2], w.x, p2); f2fma(a23[2], w.y, p2);
                u64t p3 = f2dup(P3[c]); f2fma(a01[3], w.x, p3); f2fma(a23[3], w.y, p3);
            }
        }
#pragma unroll
        for (int ch = 64; ch < 67; ch++) {
            ulonglong2 w = *(const ulonglong2*)(g_w0 + ch * 64 + o0);
            u64t p0 = f2dup(As[(k0 + 0) * 68 + ch]); f2fma(a01[0], w.x, p0); f2fma(a23[0], w.y, p0);
            u64t p1 = f2dup(As[(k0 + 1) * 68 + ch]); f2fma(a01[1], w.x, p1); f2fma(a23[1], w.y, p1);
            u64t p2 = f2dup(As[(k0 + 2) * 68 + ch]); f2fma(a01[2], w.x, p2); f2fma(a23[2], w.y, p2);
            u64t p3 = f2dup(As[(k0 + 3) * 68 + ch]); f2fma(a01[3], w.x, p3); f2fma(a23[3], w.y, p3);
        }
#pragma unroll
        for (int i = 0; i < 4; i++) {
            float r0, r1, r2, r3;
            f2unpk(a01[i], r0, r1);
            f2unpk(a23[i], r2, r3);
            float4 r = make_float4(fmaxf(r0, 0.f), fmaxf(r1, 0.f), fmaxf(r2, 0.f), fmaxf(r3, 0.f));
            *(float4*)(Bs + (k0 + i) * 68 + o0) = r;
        }
    }
    __syncthreads();

    // ---- layer 2: 64 -> 64 ----
    {
        int kq = tid >> 4, oq = tid & 15;
        int k0 = kq * 4, o0 = oq * 4;
        float4 b4 = *(const float4*)(g_bb1 + o0);
        u64t a01[4], a23[4];
#pragma unroll
        for (int i = 0; i < 4; i++) { a01[i] = f2pk(b4.x, b4.y); a23[i] = f2pk(b4.z, b4.w); }
        for (int ch = 0; ch < 64; ch += 4) {
            float4 A0 = *(const float4*)(Bs + (k0 + 0) * 68 + ch);
            float4 A1 = *(const float4*)(Bs + (k0 + 1) * 68 + ch);
            float4 A2 = *(const float4*)(Bs + (k0 + 2) * 68 + ch);
            float4 A3 = *(const float4*)(Bs + (k0 + 3) * 68 + ch);
            const float* P0 = (const float*)&A0;
            const float* P1 = (const float*)&A1;
            const float* P2 = (const float*)&A2;
            const float* P3 = (const float*)&A3;
#pragma unroll
            for (int c = 0; c < 4; c++) {
                ulonglong2 w = *(const ulonglong2*)(g_w1 + (ch + c) * 64 + o0);
                u64t p0 = f2dup(P0[c]); f2fma(a01[0], w.x, p0); f2fma(a23[0], w.y, p0);
                u64t p1 = f2dup(P1[c]); f2fma(a01[1], w.x, p1); f2fma(a23[1], w.y, p1);
                u64t p2 = f2dup(P2[c]); f2fma(a01[2], w.x, p2); f2fma(a23[2], w.y, p2);
                u64t p3 = f2dup(P3[c]); f2fma(a01[3], w.x, p3); f2fma(a23[3], w.y, p3);
            }
        }
#pragma unroll
        for (int i = 0; i < 4; i++) {
            float r0, r1, r2, r3;
            f2unpk(a01[i], r0, r1);
            f2unpk(a23[i], r2, r3);
            float4 r = make_float4(fmaxf(r0, 0.f), fmaxf(r1, 0.f), fmaxf(r2, 0.f), fmaxf(r3, 0.f));
            *(float4*)(As + (k0 + i) * 68 + o0) = r;
        }
    }
    __syncthreads();

    // ---- layer 3: 64 -> 128, 4k x 8o tile (256 tiles), weights loaded once ----
    {
        int oq = tid & 15, kq = tid >> 4;
        int o0 = oq * 8, kb = kq * 4;
        float4 bA = *(const float4*)(g_bb2 + o0);
        float4 bB = *(const float4*)(g_bb2 + o0 + 4);
        u64t acc[4][4];
#pragma unroll
        for (int k = 0; k < 4; k++) {
            acc[k][0] = f2pk(bA.x, bA.y); acc[k][1] = f2pk(bA.z, bA.w);
            acc[k][2] = f2pk(bB.x, bB.y); acc[k][3] = f2pk(bB.z, bB.w);
        }
        for (int ch = 0; ch < 64; ch += 4) {
            float4 A0 = *(const float4*)(As + (kb + 0) * 68 + ch);
            float4 A1 = *(const float4*)(As + (kb + 1) * 68 + ch);
            float4 A2 = *(const float4*)(As + (kb + 2) * 68 + ch);
            float4 A3 = *(const float4*)(As + (kb + 3) * 68 + ch);
            const float* P0 = (const float*)&A0;
            const float* P1 = (const float*)&A1;
            const float* P2 = (const float*)&A2;
            const float* P3 = (const float*)&A3;
#pragma unroll
            for (int c = 0; c < 4; c++) {
                ulonglong2 wlo = *(const ulonglong2*)(g_w2 + (ch + c) * 128 + o0);
                ulonglong2 whi = *(const ulonglong2*)(g_w2 + (ch + c) * 128 + o0 + 4);
                u64t p;
                p = f2dup(P0[c]);
                f2fma(acc[0][0], wlo.x, p); f2fma(acc[0][1], wlo.y, p);
                f2fma(acc[0][2], whi.x, p); f2fma(acc[0][3], whi.y, p);
                p = f2dup(P1[c]);
                f2fma(acc[1][0], wlo.x, p); f2fma(acc[1][1], wlo.y, p);
                f2fma(acc[1][2], whi.x, p); f2fma(acc[1][3], whi.y, p);
                p = f2dup(P2[c]);
                f2fma(acc[2][0], wlo.x, p); f2fma(acc[2][1], wlo.y, p);
                f2fma(acc[2][2], whi.x, p); f2fma(acc[2][3], whi.y, p);
                p = f2dup(P3[c]);
                f2fma(acc[3][0], wlo.x, p); f2fma(acc[3][1], wlo.y, p);
                f2fma(acc[3][2], whi.x, p); f2fma(acc[3][3], whi.y, p);
            }
        }
        float4 mxA = make_float4(NEGc, NEGc, NEGc, NEGc);
        float4 mxB = make_float4(NEGc, NEGc, NEGc, NEGc);
#pragma unroll
        for (int k = 0; k < 4; k++) {
            if (smask[kb + k]) {
                float r0, r1, r2, r3, r4, r5, r6, r7;
                f2unpk(acc[k][0], r0, r1);
                f2unpk(acc[k][1], r2, r3);
                f2unpk(acc[k][2], r4, r5);
                f2unpk(acc[k][3], r6, r7);
                mxA.x = fmaxf(mxA.x, fmaxf(r0, 0.f));
                mxA.y = fmaxf(mxA.y, fmaxf(r1, 0.f));
                mxA.z = fmaxf(mxA.z, fmaxf(r2, 0.f));
                mxA.w = fmaxf(mxA.w, fmaxf(r3, 0.f));
                mxB.x = fmaxf(mxB.x, fmaxf(r4, 0.f));
                mxB.y = fmaxf(mxB.y, fmaxf(r5, 0.f));
                mxB.z = fmaxf(mxB.z, fmaxf(r6, 0.f));
                mxB.w = fmaxf(mxB.w, fmaxf(r7, 0.f));
            }
        }
        *(float4*)(Mx + kq * 128 + o0) = mxA;
        *(float4*)(Mx + kq * 128 + o0 + 4) = mxB;
    }
    __syncthreads();

    if (tid < 128) {
        float v = NEGc;
#pragma unroll
        for (int q = 0; q < 16; q++) v = fmaxf(v, Mx[q * 128 + tid]);
        out[(size_t)(b * NSc + s) * 128 + tid] = v;
    }
}

// ---------------- launch ----------------
extern "C" void kernel_launch(void* const* d_in, const int* in_sizes, int n_in,
                              void* d_out, int out_size)
{
    const float* x   = (const float*)d_in[0];
    const float* pos = (const float*)d_in[1];
    const float* W0 = (const float*)d_in[2];
    const float* b0 = (const float*)d_in[3];
    const float* g0 = (const float*)d_in[4];
    const float* be0 = (const float*)d_in[5];
    const float* rm0 = (const float*)d_in[6];
    const float* rv0 = (const float*)d_in[7];
    const float* W1 = (const float*)d_in[8];
    const float* b1 = (const float*)d_in[9];
    const float* g1 = (const float*)d_in[10];
    const float* be1 = (const float*)d_in[11];
    const float* rm1 = (const float*)d_in[12];
    const float* rv1 = (const float*)d_in[13];
    const float* W2 = (const float*)d_in[14];
    const float* b2 = (const float*)d_in[15];
    const float* g2 = (const float*)d_in[16];
    const float* be2 = (const float*)d_in[17];
    const float* rm2 = (const float*)d_in[18];
    const float* rv2 = (const float*)d_in[19];

    float* out = (float*)d_out;
    float* out_sp = out + (size_t)BZc * NSc * 128;  // tuple output 2: sampled_pos

    const int FPS_SMEM = 3 * Nc * 4;  // 48 KB dynamic

    cudaFuncSetAttribute(fps_kernel, cudaFuncAttributeMaxDynamicSharedMemorySize, FPS_SMEM);

    fold_kernel<<<40, 256>>>(W0, b0, g0, be0, rm0, rv0,
                             W1, b1, g1, be1, rm1, rv1,
                             W2, b2, g2, be2, rm2, rv2);
    fps_kernel<<<BZc, 256, FPS_SMEM>>>(pos, out_sp);
    select_kernel<<<dim3(NSc, BZc), 256>>>(pos);
    mlp_kernel<<<dim3(NSc, BZc), 256>>>(x, pos, out, out_sp);
}

// round 7
// speedup vs baseline: 2.2060x; 1.1072x over previous
#include <cuda_runtime.h>
#include <cuda_bf16.h>

#define BZc 8
#define Nc 4096
#define CFc 64
#define NSc 1024
#define Kc 64
#define EPSc 1e-5f
#define NEGc -1e8f
#define Rc 0.2f
#define CANDMAX 1280

typedef unsigned long long u64t;

// ---------------- f32x2 packed helpers (sm_100+) ----------------
__device__ __forceinline__ u64t f2pk(float lo, float hi) {
    u64t r; asm("mov.b64 %0,{%1,%2};" : "=l"(r) : "f"(lo), "f"(hi)); return r;
}
__device__ __forceinline__ u64t f2dup(float a) {
    u64t r; asm("mov.b64 %0,{%1,%1};" : "=l"(r) : "f"(a)); return r;
}
__device__ __forceinline__ void f2unpk(u64t v, float& lo, float& hi) {
    asm("mov.b64 {%0,%1},%2;" : "=f"(lo), "=f"(hi) : "l"(v));
}
__device__ __forceinline__ u64t f2add(u64t a, u64t b) {
    u64t r; asm("add.rn.f32x2 %0,%1,%2;" : "=l"(r) : "l"(a), "l"(b)); return r;
}
__device__ __forceinline__ u64t f2mul(u64t a, u64t b) {
    u64t r; asm("mul.rn.f32x2 %0,%1,%2;" : "=l"(r) : "l"(a), "l"(b)); return r;
}
__device__ __forceinline__ void f2fma(u64t& acc, u64t w, u64t a) {
    asm("fma.rn.f32x2 %0,%1,%2,%0;" : "+l"(acc) : "l"(w), "l"(a));
}

// ---------------- scratch (no allocs allowed) ----------------
__device__ int   g_fps[BZc * NSc];
__device__ int   g_nbr[BZc * NSc * Kc];          // idx | (in_radius ? 0 : 0x80000000)
__device__ __align__(16) float g_w0[67 * 64];
__device__ __align__(16) float g_bb0[64];
__device__ __align__(16) float g_w1[64 * 64];
__device__ __align__(16) float g_bb1[64];
__device__ __align__(16) float g_w2[64 * 128];
__device__ __align__(16) float g_bb2[128];

// ---------------- fold BN (eval) into weights ----------------
__global__ void fold_kernel(
    const float* __restrict__ W0, const float* __restrict__ b0, const float* __restrict__ g0,
    const float* __restrict__ be0, const float* __restrict__ rm0, const float* __restrict__ rv0,
    const float* __restrict__ W1, const float* __restrict__ b1, const float* __restrict__ g1,
    const float* __restrict__ be1, const float* __restrict__ rm1, const float* __restrict__ rv1,
    const float* __restrict__ W2, const float* __restrict__ b2, const float* __restrict__ g2,
    const float* __restrict__ be2, const float* __restrict__ rm2, const float* __restrict__ rv2)
{
    int t = blockIdx.x * blockDim.x + threadIdx.x;
    int stride = gridDim.x * blockDim.x;
    for (int i = t; i < 67 * 64; i += stride) {
        int o = i & 63;
        g_w0[i] = W0[i] * (g0[o] * rsqrtf(rv0[o] + EPSc));
    }
    for (int i = t; i < 64; i += stride) {
        float sc = g0[i] * rsqrtf(rv0[i] + EPSc);
        g_bb0[i] = (b0[i] - rm0[i]) * sc + be0[i];
    }
    for (int i = t; i < 64 * 64; i += stride) {
        int o = i & 63;
        g_w1[i] = W1[i] * (g1[o] * rsqrtf(rv1[o] + EPSc));
    }
    for (int i = t; i < 64; i += stride) {
        float sc = g1[i] * rsqrtf(rv1[i] + EPSc);
        g_bb1[i] = (b1[i] - rm1[i]) * sc + be1[i];
    }
    for (int i = t; i < 64 * 128; i += stride) {
        int o = i & 127;
        g_w2[i] = W2[i] * (g2[o] * rsqrtf(rv2[o] + EPSc));
    }
    for (int i = t; i < 128; i += stride) {
        float sc = g2[i] * rsqrtf(rv2[i] + EPSc);
        g_bb2[i] = (b2[i] - rm2[i]) * sc + be2[i];
    }
}

// ---------------- farthest point sampling ----------------
__global__ void __launch_bounds__(256) fps_kernel(const float* __restrict__ pos,
                                                  float* __restrict__ out_sp)
{
    extern __shared__ float sm[];
    float* px = sm;
    float* py = sm + Nc;
    float* pz = sm + 2 * Nc;
    __shared__ unsigned rv_[2][8];
    __shared__ int      ri_[2][8];

    int b = blockIdx.x;
    int tid = threadIdx.x;
    int lane = tid & 31, wid = tid >> 5;
    const float* pb = pos + (size_t)b * Nc * 3;

    u64t xp[8], yp[8], zp[8];
    float ld[16];
#pragma unroll
    for (int p = 0; p < 8; p++) {
        int j0 = tid + 256 * (2 * p);
        int j1 = tid + 256 * (2 * p + 1);
        float x0 = pb[3 * j0], y0 = pb[3 * j0 + 1], z0 = pb[3 * j0 + 2];
        float x1 = pb[3 * j1], y1 = pb[3 * j1 + 1], z1 = pb[3 * j1 + 2];
        px[j0] = x0; py[j0] = y0; pz[j0] = z0;
        px[j1] = x1; py[j1] = y1; pz[j1] = z1;
        xp[p] = f2pk(x0, x1); yp[p] = f2pk(y0, y1); zp[p] = f2pk(z0, z1);
        ld[2 * p] = 1e10f; ld[2 * p + 1] = 1e10f;
    }
    __syncthreads();

    int cur = 0;
    for (int s = 0; s < NSc; s++) {
        float cx = px[cur], cy = py[cur], cz = pz[cur];
        if (tid == 0) {
            g_fps[b * NSc + s] = cur;
            out_sp[(b * NSc + s) * 3 + 0] = cx;
            out_sp[(b * NSc + s) * 3 + 1] = cy;
            out_sp[(b * NSc + s) * 3 + 2] = cz;
        }
        u64t ncx = f2dup(-cx), ncy = f2dup(-cy), ncz = f2dup(-cz);
#pragma unroll
        for (int p = 0; p < 8; p++) {
            u64t dx = f2add(xp[p], ncx);
            u64t dy = f2add(yp[p], ncy);
            u64t dz = f2add(zp[p], ncz);
            u64t d2 = f2add(f2add(f2mul(dx, dx), f2mul(dy, dy)), f2mul(dz, dz));
            float s0, s1;
            f2unpk(d2, s0, s1);
            ld[2 * p] = fminf(ld[2 * p], s0);
            ld[2 * p + 1] = fminf(ld[2 * p + 1], s1);
        }
        // tournament-tree argmax over 16 values, lowest index wins ties
        float v8[8]; int i8[8];
#pragma unroll
        for (int i = 0; i < 8; i++) {
            float a = ld[2 * i], bb2_ = ld[2 * i + 1];
            bool t = bb2_ > a;
            v8[i] = t ? bb2_ : a;
            i8[i] = tid + 256 * (2 * i + (t ? 1 : 0));
        }
        float v4[4]; int i4[4];
#pragma unroll
        for (int i = 0; i < 4; i++) {
            bool t = v8[2 * i + 1] > v8[2 * i];
            v4[i] = t ? v8[2 * i + 1] : v8[2 * i];
            i4[i] = t ? i8[2 * i + 1] : i8[2 * i];
        }
        float va, vb; int ia, ib;
        { bool t = v4[1] > v4[0]; va = t ? v4[1] : v4[0]; ia = t ? i4[1] : i4[0]; }
        { bool t = v4[3] > v4[2]; vb = t ? v4[3] : v4[2]; ib = t ? i4[3] : i4[2]; }
        bool tf = vb > va;
        float bv = tf ? vb : va;
        int   bi = tf ? ib : ia;

        unsigned bvb = __float_as_uint(bv);
        unsigned m = __reduce_max_sync(0xffffffffu, bvb);
        unsigned cand = (bvb == m) ? (unsigned)bi : 0x7FFFFFFFu;
        unsigned wmin = __reduce_min_sync(0xffffffffu, cand);

        int par = s & 1;
        if (lane == 0) { rv_[par][wid] = m; ri_[par][wid] = (int)wmin; }
        __syncthreads();
        unsigned v2 = (lane < 8) ? rv_[par][lane] : 0u;
        unsigned j2 = (lane < 8) ? (unsigned)ri_[par][lane] : 0x7FFFFFFFu;
        unsigned m2 = __reduce_max_sync(0xffffffffu, v2);
        unsigned c2 = (v2 == m2) ? j2 : 0x7FFFFFFFu;
        cur = (int)__reduce_min_sync(0xffffffffu, c2);
    }
}

// ---------------- exact top-K via bit-space bisection + pairwise rank ----------------
__global__ void __launch_bounds__(256) select_kernel(const float* __restrict__ pos)
{
    __shared__ int wred[8];
    __shared__ int s_tot;
    __shared__ int s_cnt;
    __shared__ unsigned cand_v[CANDMAX];
    __shared__ int      cand_i[CANDMAX];

    int b = blockIdx.y, s = blockIdx.x, tid = threadIdx.x;
    int lane = tid & 31, wid = tid >> 5;
    const float* pb = pos + (size_t)b * Nc * 3;
    int ci = g_fps[b * NSc + s];
    float sx = pb[3 * ci], sy = pb[3 * ci + 1], sz = pb[3 * ci + 2];
    float ss = __fadd_rn(__fadd_rn(__fmul_rn(sx, sx), __fmul_rn(sy, sy)), __fmul_rn(sz, sz));

    if (tid == 0) s_cnt = 0;

    unsigned vr[16];
#pragma unroll
    for (int i = 0; i < 16; i++) {
        int j = tid + 256 * i;
        float x = pb[3 * j], y = pb[3 * j + 1], z = pb[3 * j + 2];
        float pp = __fadd_rn(__fadd_rn(__fmul_rn(x, x), __fmul_rn(y, y)), __fmul_rn(z, z));
        float dot = __fadd_rn(__fadd_rn(__fmul_rn(sx, x), __fmul_rn(sy, y)), __fmul_rn(sz, z));
        float d2 = __fadd_rn(__fadd_rn(ss, pp), __fmul_rn(-2.0f, dot));
        float dd = sqrtf(fmaxf(d2, 0.0f));
        vr[i] = __float_as_uint(dd);
    }

    unsigned lo = 0u, hi = 0x40000000u;
    unsigned thr = hi;
    for (int it = 0; it < 32; it++) {
        unsigned m = (lo + hi) >> 1;
        int c = 0;
#pragma unroll
        for (int i = 0; i < 16; i++) c += (vr[i] < m) ? 1 : 0;
        for (int o = 16; o; o >>= 1) c += __shfl_down_sync(0xffffffffu, c, o);
        if (lane == 0) wred[wid] = c;
        __syncthreads();
        if (tid == 0) {
            int t2 = 0;
#pragma unroll
            for (int w = 0; w < 8; w++) t2 += wred[w];
            s_tot = t2;
        }
        __syncthreads();
        int tot = s_tot;
        if (tot >= Kc && tot <= 256) { thr = m; break; }
        if (tot < Kc) lo = m; else hi = m;
        if (hi - lo <= 1) { thr = hi; break; }
    }

#pragma unroll
    for (int i = 0; i < 16; i++) {
        if (vr[i] < thr) {
            int p = atomicAdd(&s_cnt, 1);
            if (p < CANDMAX) { cand_v[p] = vr[i]; cand_i[p] = tid + 256 * i; }
        }
    }
    __syncthreads();
    int c = s_cnt; if (c > CANDMAX) c = CANDMAX;

    int off = (b * NSc + s) * Kc;
    for (int q0 = tid; q0 < c; q0 += 256) {
        unsigned vi = cand_v[q0];
        int ji = cand_i[q0];
        int r = 0;
        for (int q = 0; q < c; q++) {
            unsigned vq = cand_v[q];
            int jq = cand_i[q];
            r += (vq < vi || (vq == vi && jq < ji)) ? 1 : 0;
        }
        if (r < Kc) {
            float ddv = __uint_as_float(vi);
            g_nbr[off + r] = ji | (ddv <= Rc ? 0 : 0x80000000);
        }
    }
}

// ---------------- fused MLP (67->64->64->128) + masked max pool ----------------
// Activations stored TRANSPOSED [ch][k] (stride 68). Warp-level o/k slicing so
// each warp reads only its weight slice: 1 wavefront per weight LDG, 1 per
// activation LDS. FFMA2 packed math, order-identical to prior rounds.
__global__ void __launch_bounds__(256, 3) mlp_kernel(const float* __restrict__ x,
                                                     const float* __restrict__ pos,
                                                     float* __restrict__ out,
                                                     const float* __restrict__ sp)
{
    __shared__ float As[67 * 68];   // [ch][k], stride 68
    __shared__ float Bs[64 * 68];   // [ch][k]
    __shared__ float Mx[8 * 128];
    __shared__ int nidx[64];
    __shared__ unsigned char smask[64];
    __shared__ float scp[3];

    int b = blockIdx.y, s = blockIdx.x, tid = threadIdx.x;
    int w = tid >> 5, lane = tid & 31;

    if (tid < 64) {
        int e = g_nbr[(b * NSc + s) * Kc + tid];
        nidx[tid] = e & 0x7FFFFFFF;
        smask[tid] = (e >= 0) ? 1 : 0;
    }
    if (tid < 3) scp[tid] = sp[(b * NSc + s) * 3 + tid];
    __syncthreads();

    const float* xb = x + (size_t)b * Nc * CFc;
    const float* pb = pos + (size_t)b * Nc * 3;
    // gather transposed: lanes sweep ch (coalesced LDG), write As[ch][k]
    for (int i = tid; i < 64 * 67; i += 256) {
        int k = i / 67, ch = i - k * 67;
        int id = nidx[k];
        float v = (ch < 3) ? (pb[3 * id + ch] - scp[ch]) : xb[(size_t)id * CFc + (ch - 3)];
        As[ch * 68 + k] = v;
    }
    __syncthreads();

    // ---- layer 1: 67 -> 64. warp slice: 16 o x 32 k; thread: 4k x 4o ----
    {
        int o0 = (w & 3) * 16 + (lane & 3) * 4;
        int k0 = (w >> 2) * 32 + (lane >> 2) * 4;
        float4 b4 = *(const float4*)(g_bb0 + o0);
        u64t aL[4], aH[4];
#pragma unroll
        for (int i = 0; i < 4; i++) { aL[i] = f2pk(b4.x, b4.y); aH[i] = f2pk(b4.z, b4.w); }
        for (int ch = 0; ch < 67; ch++) {
            float4 a = *(const float4*)(As + ch * 68 + k0);
            ulonglong2 wv = *(const ulonglong2*)(g_w0 + ch * 64 + o0);
            u64t d0 = f2dup(a.x); f2fma(aL[0], wv.x, d0); f2fma(aH[0], wv.y, d0);
            u64t d1 = f2dup(a.y); f2fma(aL[1], wv.x, d1); f2fma(aH[1], wv.y, d1);
            u64t d2 = f2dup(a.z); f2fma(aL[2], wv.x, d2); f2fma(aH[2], wv.y, d2);
            u64t d3 = f2dup(a.w); f2fma(aL[3], wv.x, d3); f2fma(aH[3], wv.y, d3);
        }
        float r[4][4];
#pragma unroll
        for (int i = 0; i < 4; i++) {
            f2unpk(aL[i], r[i][0], r[i][1]);
            f2unpk(aH[i], r[i][2], r[i][3]);
#pragma unroll
            for (int j = 0; j < 4; j++) r[i][j] = fmaxf(r[i][j], 0.f);
        }
#pragma unroll
        for (int j = 0; j < 4; j++)
            *(float4*)(Bs + (o0 + j) * 68 + k0) = make_float4(r[0][j], r[1][j], r[2][j], r[3][j]);
    }
    __syncthreads();

    // ---- layer 2: 64 -> 64, same tiling, Bs -> As ----
    {
        int o0 = (w & 3) * 16 + (lane & 3) * 4;
        int k0 = (w >> 2) * 32 + (lane >> 2) * 4;
        float4 b4 = *(const float4*)(g_bb1 + o0);
        u64t aL[4], aH[4];
#pragma unroll
        for (int i = 0; i < 4; i++) { aL[i] = f2pk(b4.x, b4.y); aH[i] = f2pk(b4.z, b4.w); }
        for (int ch = 0; ch < 64; ch++) {
            float4 a = *(const float4*)(Bs + ch * 68 + k0);
            ulonglong2 wv = *(const ulonglong2*)(g_w1 + ch * 64 + o0);
            u64t d0 = f2dup(a.x); f2fma(aL[0], wv.x, d0); f2fma(aH[0], wv.y, d0);
            u64t d1 = f2dup(a.y); f2fma(aL[1], wv.x, d1); f2fma(aH[1], wv.y, d1);
            u64t d2 = f2dup(a.z); f2fma(aL[2], wv.x, d2); f2fma(aH[2], wv.y, d2);
            u64t d3 = f2dup(a.w); f2fma(aL[3], wv.x, d3); f2fma(aH[3], wv.y, d3);
        }
        float r[4][4];
#pragma unroll
        for (int i = 0; i < 4; i++) {
            f2unpk(aL[i], r[i][0], r[i][1]);
            f2unpk(aH[i], r[i][2], r[i][3]);
#pragma unroll
            for (int j = 0; j < 4; j++) r[i][j] = fmaxf(r[i][j], 0.f);
        }
#pragma unroll
        for (int j = 0; j < 4; j++)
            *(float4*)(As + (o0 + j) * 68 + k0) = make_float4(r[0][j], r[1][j], r[2][j], r[3][j]);
    }
    __syncthreads();

    // ---- layer 3: 64 -> 128. warp slice: 32 o x 32 k; thread: 8k x 4o ----
    {
        int o0 = (w & 3) * 32 + (lane & 7) * 4;
        int k0 = (w >> 2) * 32 + (lane >> 3) * 8;
        float4 b4 = *(const float4*)(g_bb2 + o0);
        u64t aL[8], aH[8];
#pragma unroll
        for (int i = 0; i < 8; i++) { aL[i] = f2pk(b4.x, b4.y); aH[i] = f2pk(b4.z, b4.w); }
        for (int ch = 0; ch < 64; ch++) {
            float4 a0 = *(const float4*)(As + ch * 68 + k0);
            float4 a1 = *(const float4*)(As + ch * 68 + k0 + 4);
            ulonglong2 wv = *(const ulonglong2*)(g_w2 + ch * 128 + o0);
            u64t d;
            d = f2dup(a0.x); f2fma(aL[0], wv.x, d); f2fma(aH[0], wv.y, d);
            d = f2dup(a0.y); f2fma(aL[1], wv.x, d); f2fma(aH[1], wv.y, d);
            d = f2dup(a0.z); f2fma(aL[2], wv.x, d); f2fma(aH[2], wv.y, d);
            d = f2dup(a0.w); f2fma(aL[3], wv.x, d); f2fma(aH[3], wv.y, d);
            d = f2dup(a1.x); f2fma(aL[4], wv.x, d); f2fma(aH[4], wv.y, d);
            d = f2dup(a1.y); f2fma(aL[5], wv.x, d); f2fma(aH[5], wv.y, d);
            d = f2dup(a1.z); f2fma(aL[6], wv.x, d); f2fma(aH[6], wv.y, d);
            d = f2dup(a1.w); f2fma(aL[7], wv.x, d); f2fma(aH[7], wv.y, d);
        }
        float4 mx = make_float4(NEGc, NEGc, NEGc, NEGc);
#pragma unroll
        for (int i = 0; i < 8; i++) {
            if (smask[k0 + i]) {
                float r0, r1, r2, r3;
                f2unpk(aL[i], r0, r1);
                f2unpk(aH[i], r2, r3);
                mx.x = fmaxf(mx.x, fmaxf(r0, 0.f));
                mx.y = fmaxf(mx.y, fmaxf(r1, 0.f));
                mx.z = fmaxf(mx.z, fmaxf(r2, 0.f));
                mx.w = fmaxf(mx.w, fmaxf(r3, 0.f));
            }
        }
        int row = (w >> 2) * 4 + (lane >> 3);
        *(float4*)(Mx + row * 128 + o0) = mx;
    }
    __syncthreads();

    if (tid < 128) {
        float v = NEGc;
#pragma unroll
        for (int q = 0; q < 8; q++) v = fmaxf(v, Mx[q * 128 + tid]);
        out[(size_t)(b * NSc + s) * 128 + tid] = v;
    }
}

// ---------------- launch ----------------
extern "C" void kernel_launch(void* const* d_in, const int* in_sizes, int n_in,
                              void* d_out, int out_size)
{
    const float* x   = (const float*)d_in[0];
    const float* pos = (const float*)d_in[1];
    const float* W0 = (const float*)d_in[2];
    const float* b0 = (const float*)d_in[3];
    const float* g0 = (const float*)d_in[4];
    const float* be0 = (const float*)d_in[5];
    const float* rm0 = (const float*)d_in[6];
    const float* rv0 = (const float*)d_in[7];
    const float* W1 = (const float*)d_in[8];
    const float* b1 = (const float*)d_in[9];
    const float* g1 = (const float*)d_in[10];
    const float* be1 = (const float*)d_in[11];
    const float* rm1 = (const float*)d_in[12];
    const float* rv1 = (const float*)d_in[13];
    const float* W2 = (const float*)d_in[14];
    const float* b2 = (const float*)d_in[15];
    const float* g2 = (const float*)d_in[16];
    const float* be2 = (const float*)d_in[17];
    const float* rm2 = (const float*)d_in[18];
    const float* rv2 = (const float*)d_in[19];

    float* out = (float*)d_out;
    float* out_sp = out + (size_t)BZc * NSc * 128;  // tuple output 2: sampled_pos

    const int FPS_SMEM = 3 * Nc * 4;  // 48 KB dynamic

    cudaFuncSetAttribute(fps_kernel, cudaFuncAttributeMaxDynamicSharedMemorySize, FPS_SMEM);

    fold_kernel<<<40, 256>>>(W0, b0, g0, be0, rm0, rv0,
                             W1, b1, g1, be1, rm1, rv1,
                             W2, b2, g2, be2, rm2, rv2);
    fps_kernel<<<BZc, 256, FPS_SMEM>>>(pos, out_sp);
    select_kernel<<<dim3(NSc, BZc), 256>>>(pos);
    mlp_kernel<<<dim3(NSc, BZc), 256>>>(x, pos, out, out_sp);
}